// round 14
// baseline (speedup 1.0000x reference)
#include <cuda_runtime.h>
#include <cuda_bf16.h>
#include <cuda_fp16.h>
#include <math.h>
#include <stdint.h>

#define S_  256
#define U_  64
#define H_  512
#define H2_ 256
#define V_  5000
#define MSU 16384
#define VPAD 5120
#define PI_F 3.14159265358979323846f

/* ------------------------- device scratch ------------------------- */
__device__ float         g_T    [168 * H2_];
__device__ __nv_bfloat16 g_ench [(size_t)VPAD * H_];
__device__ __nv_bfloat16 g_encl [(size_t)VPAD * H_];
__device__ __nv_bfloat16 g_G1h  [512 * H_];
__device__ __nv_bfloat16 g_G1l  [512 * H_];
__device__ float         g_E2   [(size_t)VPAD * H_];
__device__ __nv_bfloat16 g_Th   [256 * H2_];
__device__ __nv_bfloat16 g_Tl   [256 * H2_];
__device__ __nv_bfloat16 g_G2h  [512 * H2_];
__device__ __nv_bfloat16 g_G2l  [512 * H2_];
__device__ float         g_T2   [256 * H_];
__device__ __nv_bfloat16 g_uwh  [128 * H_];
__device__ __nv_bfloat16 g_uwl  [128 * H_];
__device__ float         g_P2   [(size_t)128 * V_];
__device__ float         g_P3   [(size_t)256 * V_];
__device__ __nv_bfloat16 g_B1h  [512 * H_];
__device__ __nv_bfloat16 g_B1l  [512 * H_];
__device__ __nv_bfloat16 g_B2h  [256 * H_];
__device__ __nv_bfloat16 g_B2l  [256 * H_];
__device__ __nv_bfloat16 g_wihh [512 * H_];
__device__ __nv_bfloat16 g_wihl [512 * H_];
__device__ __half        g_whh16[512 * H_];
__device__ __half        g_fcwA16[(size_t)VPAD * H_];
__device__ __nv_bfloat16 g_fcwBh[(size_t)VPAD * H_];
__device__ __nv_bfloat16 g_fcwBl[(size_t)VPAD * H_];
__device__ __nv_bfloat16 g_fcwCh[(size_t)VPAD * H2_];
__device__ __nv_bfloat16 g_fcwCl[(size_t)VPAD * H2_];
__device__ float         g_cvec [H_];
__device__ __half        g_out16[(size_t)MSU * H_];
__device__ float         g_hfin [U_ * H_];
__device__ __half        g_w16  [(size_t)U_ * S_ * S_];
__device__ float         g_den  [(size_t)U_ * S_];
__device__ __half        g_ow16 [(size_t)MSU * H_];

/* ---------------------------- helpers ----------------------------- */
__device__ __forceinline__ uint32_t smem_u32(const void* p) {
    uint32_t a;
    asm("{ .reg .u64 t; cvta.to.shared.u64 t, %1; cvt.u32.u64 %0, t; }"
        : "=r"(a) : "l"(p));
    return a;
}
#define CP_ASYNC16(dst, src) \
    asm volatile("cp.async.cg.shared.global [%0], [%1], 16;" :: "r"(dst), "l"(src))
#define CP_COMMIT() asm volatile("cp.async.commit_group;" ::: "memory")
#define CP_WAIT(n)  asm volatile("cp.async.wait_group %0;" :: "n"(n) : "memory")
#define STS32(addr, v) \
    asm volatile("st.shared.b32 [%0], %1;" :: "r"(addr), "r"(v) : "memory")
#define LDSM4(r0, r1, r2, r3, a) \
    asm volatile("ldmatrix.sync.aligned.m8n8.x4.shared.b16 {%0,%1,%2,%3}, [%4];" \
        : "=r"(r0), "=r"(r1), "=r"(r2), "=r"(r3) : "r"(a))
#define LDSM2T(r0, r1, a) \
    asm volatile("ldmatrix.sync.aligned.m8n8.x2.trans.shared.b16 {%0,%1}, [%2];" \
        : "=r"(r0), "=r"(r1) : "r"(a))
#define LDSM4T(r0, r1, r2, r3, a) \
    asm volatile("ldmatrix.sync.aligned.m8n8.x4.trans.shared.b16 {%0,%1,%2,%3}, [%4];" \
        : "=r"(r0), "=r"(r1), "=r"(r2), "=r"(r3) : "r"(a))
#define CLUSTER_SYNC() do { \
    asm volatile("barrier.cluster.arrive.aligned;" ::: "memory"); \
    asm volatile("barrier.cluster.wait.aligned;" ::: "memory"); \
} while (0)

#define MBAR_INIT(addr, cnt) \
    asm volatile("mbarrier.init.shared.b64 [%0], %1;" :: "r"(addr), "r"(cnt) : "memory")

/* arrive (release, cluster scope) on the same smem offset in rank r */
#define MBAR_ARRIVE_CL(addr, r) \
    asm volatile("{ .reg .b32 ra; mapa.shared::cluster.u32 ra, %0, %1; " \
                 "mbarrier.arrive.release.cluster.shared::cluster.b64 _, [ra]; }" \
                 :: "r"(addr), "r"(r) : "memory")

#define MBAR_WAIT_CL(addr, parity) \
    asm volatile("{\n\t.reg .pred P;\n\t" \
        "WL_%=:\n\t" \
        "mbarrier.try_wait.parity.acquire.cluster.shared::cta.b64 P, [%0], %1, 0x989680;\n\t" \
        "@P bra.uni WD_%=;\n\t" \
        "bra.uni WL_%=;\n\t" \
        "WD_%=:\n\t}" :: "r"(addr), "r"(parity) : "memory")

__device__ __forceinline__ void st_cluster_b32(uint32_t addr, uint32_t rank, uint32_t v) {
    asm volatile(
        "{ .reg .b32 ra; mapa.shared::cluster.u32 ra, %0, %1; "
        "st.shared::cluster.b32 [ra], %2; }"
        :: "r"(addr), "r"(rank), "r"(v) : "memory");
}
__device__ __forceinline__ float tanh_fast(float v) {
    float r; asm("tanh.approx.f32 %0, %1;" : "=f"(r) : "f"(v)); return r;
}
__device__ __forceinline__ void mma16816(float* c, const uint32_t* a, const uint32_t* b)
{
    asm volatile(
        "mma.sync.aligned.m16n8k16.row.col.f32.bf16.bf16.f32 "
        "{%0,%1,%2,%3}, {%4,%5,%6,%7}, {%8,%9}, {%0,%1,%2,%3};"
        : "+f"(c[0]), "+f"(c[1]), "+f"(c[2]), "+f"(c[3])
        : "r"(a[0]), "r"(a[1]), "r"(a[2]), "r"(a[3]), "r"(b[0]), "r"(b[1]));
}
__device__ __forceinline__ void mma16816h(float* c, const uint32_t* a, const uint32_t* b)
{
    asm volatile(
        "mma.sync.aligned.m16n8k16.row.col.f32.f16.f16.f32 "
        "{%0,%1,%2,%3}, {%4,%5,%6,%7}, {%8,%9}, {%0,%1,%2,%3};"
        : "+f"(c[0]), "+f"(c[1]), "+f"(c[2]), "+f"(c[3])
        : "r"(a[0]), "r"(a[1]), "r"(a[2]), "r"(a[3]), "r"(b[0]), "r"(b[1]));
}
__device__ __forceinline__ void split2(float v, __nv_bfloat16& h, __nv_bfloat16& l)
{
    h = __float2bfloat16(v);
    l = __float2bfloat16(v - __bfloat162float(h));
}

/* -------------- batched split-bf16 HMMA GEMM (3-term) -------------- */
struct GemmTask {
    const __nv_bfloat16 *Ah, *Al, *Bh, *Bl;
    const float* bias1;
    float* Cf;
    __nv_bfloat16 *Ch, *Cl;
    int K, Nreal, nx;
};

#define SWH 40
#define STAGE_B  61440
#define OFF_AL   10240
#define OFF_BH   20480
#define OFF_BL   40960
#define GEMM_SMEM (2 * STAGE_B)

__global__ __launch_bounds__(256, 1)
void hmma_gemm_b(GemmTask t0, GemmTask t1, GemmTask t2, GemmTask t3,
                 int c0, int c1, int c2, int c3)
{
    extern __shared__ char smem[];
    const uint32_t sbase = smem_u32(smem);
    const int tid  = threadIdx.x;

    GemmTask t;
    int lin = blockIdx.x;
    if (lin < c0)                    { t = t0; }
    else if ((lin -= c0) < c1)       { t = t1; }
    else if ((lin -= c1) < c2)       { t = t2; }
    else                             { lin -= c2; t = t3; }
    const int m0 = (lin / t.nx) * 128;
    const int n0 = (lin % t.nx) * 256;
    const __nv_bfloat16* __restrict__ Ah = t.Ah;
    const __nv_bfloat16* __restrict__ Al = t.Al;
    const __nv_bfloat16* __restrict__ Bh = t.Bh;
    const __nv_bfloat16* __restrict__ Bl = t.Bl;
    const int K = t.K, Nreal = t.Nreal;

    const int warp = tid >> 5, lane = tid & 31;
    const int wm = warp >> 2, wn = warp & 3;
    const int g  = lane >> 2, tig = lane & 3;
    const int L = K >> 5;

    const uint32_t aoffc = ((uint32_t)(wm * 64 + (lane & 15)) * SWH) * 2u
                         + (uint32_t)(lane >> 4) * 16u;
    const int sel  = (lane >> 3) & 3;
    const uint32_t boffc = ((uint32_t)(wn * 64 + ((sel & 2) << 2) + (lane & 7)) * SWH) * 2u
                         + (uint32_t)(sel & 1) * 16u;

    float acc[4][8][4];
#pragma unroll
    for (int mi = 0; mi < 4; mi++)
#pragma unroll
        for (int ni = 0; ni < 8; ni++)
#pragma unroll
            for (int q = 0; q < 4; q++) acc[mi][ni][q] = 0.0f;

    auto load_stage = [&](int chunk, int buf) {
        const uint32_t sg = sbase + (uint32_t)buf * STAGE_B;
        const int k0 = chunk << 5;
#pragma unroll 2
        for (int idx = tid; idx < 512; idx += 256) {
            int r = idx >> 2, c = idx & 3;
            uint32_t dsto = (uint32_t)(r * SWH + c * 8) * 2u;
            size_t srco = (size_t)(m0 + r) * K + k0 + c * 8;
            CP_ASYNC16(sg + dsto,            Ah + srco);
            CP_ASYNC16(sg + OFF_AL + dsto,   Al + srco);
        }
#pragma unroll 4
        for (int idx = tid; idx < 1024; idx += 256) {
            int r = idx >> 2, c = idx & 3;
            uint32_t dsto = (uint32_t)(r * SWH + c * 8) * 2u;
            size_t srco = (size_t)(n0 + r) * K + k0 + c * 8;
            CP_ASYNC16(sg + OFF_BH + dsto,   Bh + srco);
            CP_ASYNC16(sg + OFF_BL + dsto,   Bl + srco);
        }
        CP_COMMIT();
    };

    load_stage(0, 0);

    for (int i = 0; i < L; i++) {
        if (i + 1 < L) { load_stage(i + 1, (i + 1) & 1); CP_WAIT(1); }
        else           { CP_WAIT(0); }
        __syncthreads();

        const uint32_t sg = sbase + (uint32_t)(i & 1) * STAGE_B;
#pragma unroll
        for (int ks = 0; ks < 2; ks++) {
            const uint32_t kb = (uint32_t)ks * 32u;
            uint32_t ah[4][4], al[4][4], bb[8][2];
#pragma unroll
            for (int mi = 0; mi < 4; mi++)
                LDSM4(ah[mi][0], ah[mi][1], ah[mi][2], ah[mi][3],
                      sg + kb + aoffc + (uint32_t)mi * (16 * SWH * 2));
#pragma unroll
            for (int n2 = 0; n2 < 4; n2++)
                LDSM4(bb[2*n2][0], bb[2*n2][1], bb[2*n2+1][0], bb[2*n2+1][1],
                      sg + OFF_BH + kb + boffc + (uint32_t)n2 * (16 * SWH * 2));
#pragma unroll
            for (int mi = 0; mi < 4; mi++)
#pragma unroll
                for (int ni = 0; ni < 8; ni++)
                    mma16816(acc[mi][ni], ah[mi], bb[ni]);
#pragma unroll
            for (int mi = 0; mi < 4; mi++)
                LDSM4(al[mi][0], al[mi][1], al[mi][2], al[mi][3],
                      sg + OFF_AL + kb + aoffc + (uint32_t)mi * (16 * SWH * 2));
#pragma unroll
            for (int mi = 0; mi < 4; mi++)
#pragma unroll
                for (int ni = 0; ni < 8; ni++)
                    mma16816(acc[mi][ni], al[mi], bb[ni]);
#pragma unroll
            for (int n2 = 0; n2 < 4; n2++)
                LDSM4(bb[2*n2][0], bb[2*n2][1], bb[2*n2+1][0], bb[2*n2+1][1],
                      sg + OFF_BL + kb + boffc + (uint32_t)n2 * (16 * SWH * 2));
#pragma unroll
            for (int mi = 0; mi < 4; mi++)
#pragma unroll
                for (int ni = 0; ni < 8; ni++)
                    mma16816(acc[mi][ni], ah[mi], bb[ni]);
        }
        __syncthreads();
    }

#pragma unroll
    for (int mi = 0; mi < 4; mi++) {
        const int row0 = m0 + wm * 64 + mi * 16 + g;
#pragma unroll
        for (int ni = 0; ni < 8; ni++) {
            const int n = n0 + wn * 64 + ni * 8 + tig * 2;
#pragma unroll
            for (int q = 0; q < 4; q++) {
                int rr = row0 + ((q >= 2) ? 8 : 0);
                int nn = n + (q & 1);
                if (nn >= Nreal) continue;
                float f = acc[mi][ni][q];
                if (t.bias1) f += t.bias1[nn];
                if (t.Cf) {
                    t.Cf[(size_t)rr * Nreal + nn] = f;
                } else {
                    __nv_bfloat16 hi, lo;
                    split2(f, hi, lo);
                    t.Ch[(size_t)rr * Nreal + nn] = hi;
                    t.Cl[(size_t)rr * Nreal + nn] = lo;
                }
            }
        }
    }
}

/* ----------------- fp16 HMMA GEMM (final projection) --------------- */
#define SWH2      72
#define G16_OFFB  18432
#define G16_STAGE 55296
#define GEMM16_SMEM (2 * G16_STAGE)

__global__ __launch_bounds__(256, 1)
void hmma_gemm16(const __half* __restrict__ A, const __half* __restrict__ B,
                 const float* __restrict__ bias1,
                 const float* __restrict__ add1,
                 const float* __restrict__ add2, const int* __restrict__ idx2,
                 float* __restrict__ Cf, int K, int Nreal)
{
    extern __shared__ char smem[];
    const uint32_t sbase = smem_u32(smem);
    const int tid  = threadIdx.x;
    const int m0   = blockIdx.y * 128;
    const int n0   = blockIdx.x * 256;
    const int warp = tid >> 5, lane = tid & 31;
    const int wm = warp >> 2, wn = warp & 3;
    const int g  = lane >> 2, tig = lane & 3;
    const int L = K >> 6;

    const uint32_t aoffc = ((uint32_t)(wm * 64 + (lane & 15)) * SWH2) * 2u
                         + (uint32_t)(lane >> 4) * 16u;
    const int sel  = (lane >> 3) & 3;
    const uint32_t boffc = ((uint32_t)(wn * 64 + ((sel & 2) << 2) + (lane & 7)) * SWH2) * 2u
                         + (uint32_t)(sel & 1) * 16u;

    float acc[4][8][4];
#pragma unroll
    for (int mi = 0; mi < 4; mi++)
#pragma unroll
        for (int ni = 0; ni < 8; ni++)
#pragma unroll
            for (int q = 0; q < 4; q++) acc[mi][ni][q] = 0.0f;

    auto load_stage = [&](int chunk, int buf) {
        const uint32_t sg = sbase + (uint32_t)buf * G16_STAGE;
        const int k0 = chunk << 6;
#pragma unroll 4
        for (int idx = tid; idx < 1024; idx += 256) {
            int r = idx >> 3, c = idx & 7;
            CP_ASYNC16(sg + (uint32_t)(r * SWH2 + c * 8) * 2u,
                       A + (size_t)(m0 + r) * K + k0 + c * 8);
        }
#pragma unroll 8
        for (int idx = tid; idx < 2048; idx += 256) {
            int r = idx >> 3, c = idx & 7;
            CP_ASYNC16(sg + G16_OFFB + (uint32_t)(r * SWH2 + c * 8) * 2u,
                       B + (size_t)(n0 + r) * K + k0 + c * 8);
        }
        CP_COMMIT();
    };

    load_stage(0, 0);

    for (int i = 0; i < L; i++) {
        if (i + 1 < L) { load_stage(i + 1, (i + 1) & 1); CP_WAIT(1); }
        else           { CP_WAIT(0); }
        __syncthreads();

        const uint32_t sg = sbase + (uint32_t)(i & 1) * G16_STAGE;
#pragma unroll
        for (int ks = 0; ks < 4; ks++) {
            const uint32_t kb = (uint32_t)ks * 32u;
            uint32_t ah[4][4], bb[8][2];
#pragma unroll
            for (int mi = 0; mi < 4; mi++)
                LDSM4(ah[mi][0], ah[mi][1], ah[mi][2], ah[mi][3],
                      sg + kb + aoffc + (uint32_t)mi * (16 * SWH2 * 2));
#pragma unroll
            for (int n2 = 0; n2 < 4; n2++)
                LDSM4(bb[2*n2][0], bb[2*n2][1], bb[2*n2+1][0], bb[2*n2+1][1],
                      sg + G16_OFFB + kb + boffc + (uint32_t)n2 * (16 * SWH2 * 2));
#pragma unroll
            for (int mi = 0; mi < 4; mi++)
#pragma unroll
                for (int ni = 0; ni < 8; ni++)
                    mma16816h(acc[mi][ni], ah[mi], bb[ni]);
        }
        __syncthreads();
    }

#pragma unroll
    for (int mi = 0; mi < 4; mi++) {
        const int row0 = m0 + wm * 64 + mi * 16 + g;
        int i2[2] = { 0, 0 };
        if (add2) { i2[0] = idx2[row0]; i2[1] = idx2[row0 + 8]; }
#pragma unroll
        for (int ni = 0; ni < 8; ni++) {
            const int n = n0 + wn * 64 + ni * 8 + tig * 2;
#pragma unroll
            for (int q = 0; q < 4; q++) {
                int rr = row0 + ((q >= 2) ? 8 : 0);
                int nn = n + (q & 1);
                if (nn >= Nreal) continue;
                float f = acc[mi][ni][q] + bias1[nn]
                        + add1[(size_t)(rr & 63) * Nreal + nn]
                        + add2[(size_t)i2[q >> 1] * Nreal + nn];
                Cf[(size_t)rr * Nreal + nn] = f;
            }
        }
    }
}

/* ------------------------- attention HMMA -------------------------- */
#define ATT_SWA   40
#define ATT_SWB   264
#define ATT_B_OFF (128 * ATT_SWA * 2)
#define ATT_STAGE (ATT_B_OFF + 32 * ATT_SWB * 2)
#define ATT_SMEM  (2 * ATT_STAGE)

__global__ __launch_bounds__(256, 1)
void k_att_mma(const __half* __restrict__ w16, const __half* __restrict__ o16,
               const float* __restrict__ den, __half* __restrict__ ow)
{
    extern __shared__ char smem[];
    const uint32_t sbase = smem_u32(smem);
    const int tid  = threadIdx.x;
    const int u    = blockIdx.z;
    const int i0   = blockIdx.y * 128;
    const int h0   = blockIdx.x * 256;
    const int warp = tid >> 5, lane = tid & 31;
    const int wm = warp >> 2, wn = warp & 3;
    const int g  = lane >> 2, tig = lane & 3;
    const int L  = (i0 + 128) >> 5;

    const uint32_t aoffc = ((uint32_t)(wm * 64 + (lane & 15)) * ATT_SWA) * 2u
                         + (uint32_t)(lane >> 4) * 16u;
    const uint32_t boffc = ((uint32_t)((lane & 7) + ((lane >> 3) & 1) * 8) * ATT_SWB) * 2u
                         + (uint32_t)(lane >> 4) * 16u;

    float acc[4][8][4];
#pragma unroll
    for (int mi = 0; mi < 4; mi++)
#pragma unroll
        for (int ni = 0; ni < 8; ni++)
#pragma unroll
            for (int q = 0; q < 4; q++) acc[mi][ni][q] = 0.0f;

    auto load_stage = [&](int chunk, int buf) {
        const uint32_t sg = sbase + (uint32_t)buf * ATT_STAGE;
        const int j0 = chunk << 5;
#pragma unroll 2
        for (int idx = tid; idx < 512; idx += 256) {
            int r = idx >> 2, c = idx & 3;
            CP_ASYNC16(sg + (uint32_t)(r * ATT_SWA + c * 8) * 2u,
                       w16 + (size_t)u * (S_ * S_) + (size_t)(i0 + r) * S_ + j0 + c * 8);
        }
#pragma unroll 4
        for (int idx = tid; idx < 1024; idx += 256) {
            int r = idx >> 5, c = idx & 31;
            CP_ASYNC16(sg + ATT_B_OFF + (uint32_t)(r * ATT_SWB + c * 8) * 2u,
                       o16 + ((size_t)(j0 + r) * U_ + u) * H_ + h0 + c * 8);
        }
        CP_COMMIT();
    };

    load_stage(0, 0);

    for (int i = 0; i < L; i++) {
        if (i + 1 < L) { load_stage(i + 1, (i + 1) & 1); CP_WAIT(1); }
        else           { CP_WAIT(0); }
        __syncthreads();

        const uint32_t sg = sbase + (uint32_t)(i & 1) * ATT_STAGE;
#pragma unroll
        for (int ks = 0; ks < 2; ks++) {
            uint32_t ah[4][4], bb[8][2];
#pragma unroll
            for (int mi = 0; mi < 4; mi++)
                LDSM4(ah[mi][0], ah[mi][1], ah[mi][2], ah[mi][3],
                      sg + (uint32_t)ks * 32u + aoffc + (uint32_t)mi * (16 * ATT_SWA * 2));
#pragma unroll
            for (int n2 = 0; n2 < 4; n2++)
                LDSM4T(bb[2*n2][0], bb[2*n2][1], bb[2*n2+1][0], bb[2*n2+1][1],
                       sg + ATT_B_OFF + (uint32_t)ks * (16 * ATT_SWB * 2) + boffc
                          + (uint32_t)(wn * 64 + n2 * 16) * 2u);
#pragma unroll
            for (int mi = 0; mi < 4; mi++)
#pragma unroll
                for (int ni = 0; ni < 8; ni++)
                    mma16816h(acc[mi][ni], ah[mi], bb[ni]);
        }
        __syncthreads();
    }

#pragma unroll
    for (int mi = 0; mi < 4; mi++) {
        const int ia = i0 + wm * 64 + mi * 16 + g;
        const float d0 = 1.0f / den[u * S_ + ia];
        const float d1 = 1.0f / den[u * S_ + ia + 8];
#pragma unroll
        for (int ni = 0; ni < 8; ni++) {
            const int h = h0 + wn * 64 + ni * 8 + tig * 2;
            uint32_t p0 = (uint32_t)__half_as_ushort(__float2half(acc[mi][ni][0] * d0))
                        | ((uint32_t)__half_as_ushort(__float2half(acc[mi][ni][1] * d0)) << 16);
            uint32_t p1 = (uint32_t)__half_as_ushort(__float2half(acc[mi][ni][2] * d1))
                        | ((uint32_t)__half_as_ushort(__float2half(acc[mi][ni][3] * d1)) << 16);
            ((uint32_t*)ow)[(((size_t)ia      * U_ + u) * H_ + h) >> 1] = p0;
            ((uint32_t*)ow)[(((size_t)(ia + 8)* U_ + u) * H_ + h) >> 1] = p1;
        }
    }
}

/* ----------------------- vectorized splits ------------------------- */
__global__ __launch_bounds__(256)
void k_split8(const float* __restrict__ src, int pitch, int col0, int lcols,
              int rows, int padRows,
              __nv_bfloat16* __restrict__ dh, __nv_bfloat16* __restrict__ dl)
{
    const int cmask = (1 << lcols) - 1;
    const size_t total8 = ((size_t)padRows << lcols) >> 3;
    for (size_t gidx = (size_t)blockIdx.x * blockDim.x + threadIdx.x;
         gidx < total8; gidx += (size_t)gridDim.x * blockDim.x) {
        size_t idx = gidx << 3;
        int r = (int)(idx >> lcols);
        int c = (int)idx & cmask;
        float4 v0, v1;
        if (r < rows) {
            const float* p = src + (size_t)r * pitch + col0 + c;
            v0 = *(const float4*)p;
            v1 = *(const float4*)(p + 4);
        } else {
            v0 = make_float4(0.f, 0.f, 0.f, 0.f);
            v1 = v0;
        }
        float vv[8] = { v0.x, v0.y, v0.z, v0.w, v1.x, v1.y, v1.z, v1.w };
        uint32_t hp[4], lp[4];
#pragma unroll
        for (int i = 0; i < 4; i++) {
            __nv_bfloat16 h0, l0, h1, l1;
            split2(vv[2 * i],     h0, l0);
            split2(vv[2 * i + 1], h1, l1);
            hp[i] = (uint32_t)*(uint16_t*)&h0 | ((uint32_t)*(uint16_t*)&h1 << 16);
            lp[i] = (uint32_t)*(uint16_t*)&l0 | ((uint32_t)*(uint16_t*)&l1 << 16);
        }
        *(uint4*)(dh + idx) = make_uint4(hp[0], hp[1], hp[2], hp[3]);
        *(uint4*)(dl + idx) = make_uint4(lp[0], lp[1], lp[2], lp[3]);
    }
}

__global__ __launch_bounds__(256)
void k_split8h(const float* __restrict__ src, int pitch, int col0, int lcols,
               int rows, int padRows, __half* __restrict__ d)
{
    const int cmask = (1 << lcols) - 1;
    const size_t total8 = ((size_t)padRows << lcols) >> 3;
    for (size_t gidx = (size_t)blockIdx.x * blockDim.x + threadIdx.x;
         gidx < total8; gidx += (size_t)gridDim.x * blockDim.x) {
        size_t idx = gidx << 3;
        int r = (int)(idx >> lcols);
        int c = (int)idx & cmask;
        float4 v0, v1;
        if (r < rows) {
            const float* p = src + (size_t)r * pitch + col0 + c;
            v0 = *(const float4*)p;
            v1 = *(const float4*)(p + 4);
        } else {
            v0 = make_float4(0.f, 0.f, 0.f, 0.f);
            v1 = v0;
        }
        float vv[8] = { v0.x, v0.y, v0.z, v0.w, v1.x, v1.y, v1.z, v1.w };
        uint32_t hp[4];
#pragma unroll
        for (int i = 0; i < 4; i++) {
            __half a = __float2half(vv[2 * i]);
            __half b = __float2half(vv[2 * i + 1]);
            hp[i] = (uint32_t)__half_as_ushort(a) | ((uint32_t)__half_as_ushort(b) << 16);
        }
        *(uint4*)(d + idx) = make_uint4(hp[0], hp[1], hp[2], hp[3]);
    }
}

/* transpose-split */
__global__ __launch_bounds__(256)
void k_split_t(const float* __restrict__ src, int pitch, int col0, int crows,
               __nv_bfloat16* __restrict__ dh, __nv_bfloat16* __restrict__ dl)
{
    const size_t total = (size_t)crows << 9;
    for (size_t idx = (size_t)blockIdx.x * blockDim.x + threadIdx.x;
         idx < total; idx += (size_t)gridDim.x * blockDim.x) {
        int c = (int)(idx >> 9);
        int o = (int)idx & 511;
        float v = src[(size_t)o * pitch + col0 + c];
        __nv_bfloat16 hi, lo;
        split2(v, hi, lo);
        dh[idx] = hi; dl[idx] = lo;
    }
}

/* ----------------------------- misc -------------------------------- */
__global__ void k_userw(const float* __restrict__ user_w, const int* __restrict__ au)
{
    const int u = blockIdx.x;
    const int c = threadIdx.x;
    float v = 0.0f;
    if (u < U_) v = user_w[(size_t)au[u] * H_ + c];
    __nv_bfloat16 hi, lo;
    split2(v, hi, lo);
    g_uwh[u * H_ + c] = hi;
    g_uwl[u * H_ + c] = lo;
}

__global__ void k_cvec(const float* __restrict__ fcpt_b, const float* __restrict__ W_ih,
                       const float* __restrict__ b_ih, const float* __restrict__ b_hh)
{
    const int n = blockIdx.x * blockDim.x + threadIdx.x;
    if (n >= H_) return;
    float a = b_ih[n] + b_hh[n];
    for (int k = 0; k < H_; k++) a += fcpt_b[k] * W_ih[(size_t)n * H_ + k];
    g_cvec[n] = a;
}

__global__ void k_week(const float* __restrict__ sigma,
                       const float* __restrict__ wwi,
                       const int*   __restrict__ wm,
                       const float* __restrict__ wenc)
{
    const int slot = blockIdx.x;
    const int tid  = threadIdx.x;
    __shared__ float ww[168];
    __shared__ float red[256];

    float sig    = fabsf(sigma[slot]);
    float inv2s2 = 1.0f / (2.0f * sig * sig);
    float coef   = rsqrtf(2.0f * PI_F * sig * sig);

    float v = 0.0f;
    if (tid < 168) {
        float x = wwi[slot * 168 + tid];
        v = coef * expf(-x * x * inv2s2);
        ww[tid] = v;
    }
    red[tid] = v;
    __syncthreads();
    for (int off = 128; off > 0; off >>= 1) {
        if (tid < off) red[tid] += red[tid + off];
        __syncthreads();
    }
    const float inv = 1.0f / red[0];

    float acc = 0.0f;
    for (int k = 0; k < 168; k++) {
        int row = wm[slot * 168 + k];
        acc += (ww[k] * inv) * wenc[row * H2_ + tid];
    }
    g_T[slot * H2_ + tid] = acc;
}

/* --------- RNN v4: cluster(4), mbarrier sync, 4 MMA chains ---------- */
#define RWPAD 520
#define R3_WST  0
#define R3_HB0  133120
#define R3_HB1  141312
#define R3_MB   149504
#define RNN3_SMEM 149520

__global__ __cluster_dims__(4, 1, 1) __launch_bounds__(256, 1)
void k_rnn3(const float* __restrict__ E2, const float* __restrict__ T2,
            const int* __restrict__ x, const int* __restrict__ ts,
            const __half* __restrict__ Whh16, const float* __restrict__ h0,
            __half* __restrict__ out16, float* __restrict__ hfin, int steps)
{
    extern __shared__ char sm[];
    const uint32_t sb = smem_u32(sm);
    const int tid = threadIdx.x;
    const int warp = tid >> 5, lane = tid & 31;
    const int ug = blockIdx.x >> 2;
    uint32_t rank;
    asm("mov.u32 %0, %%cluster_ctarank;" : "=r"(rank));
    const int row0 = (int)rank * 128;

    if (tid == 0) {
        MBAR_INIT(sb + R3_MB,     1024);
        MBAR_INIT(sb + R3_MB + 8, 1024);
    }

    /* stage W rows [row0, row0+128) via vectorized fp16 copies */
    __half* wst = (__half*)(sm + R3_WST);
    for (int idx = tid; idx < 128 * 64; idx += 256) {
        int r = idx >> 6, c8 = (idx & 63) << 3;
        uint4 v = *(const uint4*)&Whh16[(size_t)(row0 + r) * H_ + c8];
        *(uint4*)&wst[r * RWPAD + c8] = v;
    }
    __syncthreads();

    uint32_t A[32][4];
    {
        const uint32_t la = (uint32_t)(lane & 15) * (RWPAD * 2)
                          + (uint32_t)(lane >> 4) * 16u;
        const uint32_t wbase = sb + R3_WST + (uint32_t)warp * 16u * (RWPAD * 2);
#pragma unroll
        for (int kt = 0; kt < 32; kt++)
            LDSM4(A[kt][0], A[kt][1], A[kt][2], A[kt][3],
                  wbase + la + (uint32_t)kt * 32u);
    }

    __half* hb0p = (__half*)(sm + R3_HB0);
    for (int idx = tid; idx < 512 * 8; idx += 256) {
        int k = idx >> 3, u = idx & 7;
        hb0p[k * 8 + u] = __float2half(h0[(size_t)(ug * 8 + u) * H_ + k]);
    }
    __syncthreads();
    CLUSTER_SYNC();            /* peers' mbarriers initialized + hb0 ready */

    const int g = lane >> 2, tig = lane & 3;
    const int kr0 = row0 + warp * 16 + g;
    const int u0 = ug * 8 + tig * 2;
    const uint32_t lb16 = (uint32_t)(lane & 15) * 16u;

    float pv[4];
    {
        int xa = __ldg(x + u0), xb = __ldg(x + u0 + 1);
        int ta = __ldg(ts + u0), tb = __ldg(ts + u0 + 1);
        pv[0] = __ldg(E2 + (size_t)xa * H_ + kr0)     + __ldg(T2 + (size_t)ta * H_ + kr0);
        pv[1] = __ldg(E2 + (size_t)xb * H_ + kr0)     + __ldg(T2 + (size_t)tb * H_ + kr0);
        pv[2] = __ldg(E2 + (size_t)xa * H_ + kr0 + 8) + __ldg(T2 + (size_t)ta * H_ + kr0 + 8);
        pv[3] = __ldg(E2 + (size_t)xb * H_ + kr0 + 8) + __ldg(T2 + (size_t)tb * H_ + kr0 + 8);
    }

    int ph[2] = { 0, 0 };

    for (int s = 0; s < steps; s++) {
        const uint32_t hb = sb + ((s & 1) ? R3_HB1 : R3_HB0);

        /* 4 independent MMA chains of depth 8 */
        float a0[4] = {0.f,0.f,0.f,0.f}, a1[4] = {0.f,0.f,0.f,0.f};
        float a2[4] = {0.f,0.f,0.f,0.f}, a3[4] = {0.f,0.f,0.f,0.f};
#pragma unroll
        for (int kt = 0; kt < 32; kt += 4) {
            uint32_t b0[2], b1[2], b2[2], b3[2];
            LDSM2T(b0[0], b0[1], hb + (uint32_t)((kt + 0) * 16) * 16u + lb16);
            LDSM2T(b1[0], b1[1], hb + (uint32_t)((kt + 1) * 16) * 16u + lb16);
            LDSM2T(b2[0], b2[1], hb + (uint32_t)((kt + 2) * 16) * 16u + lb16);
            LDSM2T(b3[0], b3[1], hb + (uint32_t)((kt + 3) * 16) * 16u + lb16);
            mma16816h(a0, A[kt + 0], b0);
            mma16816h(a1, A[kt + 1], b1);
            mma16816h(a2, A[kt + 2], b2);
            mma16816h(a3, A[kt + 3], b3);
        }
        float acc[4];
#pragma unroll
        for (int q = 0; q < 4; q++) acc[q] = (a0[q] + a1[q]) + (a2[q] + a3[q]);

        float hv0 = tanh_fast(pv[0] + acc[0]);
        float hv1 = tanh_fast(pv[1] + acc[1]);
        float hv2 = tanh_fast(pv[2] + acc[2]);
        float hv3 = tanh_fast(pv[3] + acc[3]);

        const size_t ob = (size_t)s * U_ * H_;
        if (s == steps - 1) {
            out16[ob + (size_t)u0 * H_ + kr0]           = __float2half(hv0);
            out16[ob + (size_t)(u0 + 1) * H_ + kr0]     = __float2half(hv1);
            out16[ob + (size_t)u0 * H_ + kr0 + 8]       = __float2half(hv2);
            out16[ob + (size_t)(u0 + 1) * H_ + kr0 + 8] = __float2half(hv3);
            hfin[(size_t)u0 * H_ + kr0]           = hv0;
            hfin[(size_t)(u0 + 1) * H_ + kr0]     = hv1;
            hfin[(size_t)u0 * H_ + kr0 + 8]       = hv2;
            hfin[(size_t)(u0 + 1) * H_ + kr0 + 8] = hv3;
        } else {
            const int nb = (s + 1) & 1;
            uint32_t p0 = (uint32_t)__half_as_ushort(__float2half(hv0))
                        | ((uint32_t)__half_as_ushort(__float2half(hv1)) << 16);
            uint32_t p1 = (uint32_t)__half_as_ushort(__float2half(hv2))
                        | ((uint32_t)__half_as_ushort(__float2half(hv3)) << 16);
            const uint32_t nbo = (nb ? R3_HB1 : R3_HB0);
            uint32_t d0 = sb + nbo + (uint32_t)(kr0 * 8 + tig * 2) * 2u;
            uint32_t d1 = sb + nbo + (uint32_t)((kr0 + 8) * 8 + tig * 2) * 2u;
#pragma unroll
            for (int r = 0; r < 4; r++) {
                if ((uint32_t)r == rank) { STS32(d0, p0); STS32(d1, p1); }
                else {
                    st_cluster_b32(d0, (uint32_t)r, p0);
                    st_cluster_b32(d1, (uint32_t)r, p1);
                }
            }
            /* publish: arrive (release) on all ranks' barrier for buffer nb */
            const uint32_t mbo = sb + R3_MB + (uint32_t)nb * 8u;
#pragma unroll
            for (int r = 0; r < 4; r++)
                MBAR_ARRIVE_CL(mbo, (uint32_t)r);

            /* off-critical-path work inside the wait window */
            out16[ob + (size_t)u0 * H_ + kr0]           = __float2half(hv0);
            out16[ob + (size_t)(u0 + 1) * H_ + kr0]     = __float2half(hv1);
            out16[ob + (size_t)u0 * H_ + kr0 + 8]       = __float2half(hv2);
            out16[ob + (size_t)(u0 + 1) * H_ + kr0 + 8] = __float2half(hv3);
            const int s1o = (s + 1) * U_;
            int xa = __ldg(x + s1o + u0), xb = __ldg(x + s1o + u0 + 1);
            int ta = __ldg(ts + s1o + u0), tb = __ldg(ts + s1o + u0 + 1);
            float n0 = __ldg(E2 + (size_t)xa * H_ + kr0)     + __ldg(T2 + (size_t)ta * H_ + kr0);
            float n1 = __ldg(E2 + (size_t)xb * H_ + kr0)     + __ldg(T2 + (size_t)tb * H_ + kr0);
            float n2 = __ldg(E2 + (size_t)xa * H_ + kr0 + 8) + __ldg(T2 + (size_t)ta * H_ + kr0 + 8);
            float n3 = __ldg(E2 + (size_t)xb * H_ + kr0 + 8) + __ldg(T2 + (size_t)tb * H_ + kr0 + 8);

            MBAR_WAIT_CL(mbo, ph[nb]);
            ph[nb] ^= 1;
            pv[0] = n0; pv[1] = n1; pv[2] = n2; pv[3] = n3;
        }
    }
}

/* ------------------- attention weights + den ----------------------- */
__global__ void k_w(const float* __restrict__ t, const float* __restrict__ s)
{
    const int i = blockIdx.x, u = blockIdx.y;
    const int j = threadIdx.x;
    __shared__ float red[256];

    float wv = 0.0f;
    if (j <= i) {
        float dt = t[i * U_ + u] - t[j * U_ + u];
        float d0 = s[((size_t)i * U_ + u) * 2 + 0] - s[((size_t)j * U_ + u) * 2 + 0];
        float d1 = s[((size_t)i * U_ + u) * 2 + 1] - s[((size_t)j * U_ + u) * 2 + 1];
        float ds = sqrtf(d0 * d0 + d1 * d1);
        float ft = (cosf(dt * (2.0f * PI_F / 86400.0f)) + 1.0f) * 0.5f
                 * expf(-(dt / 86400.0f) * 0.1f);
        float fs = expf(-ds * 100.0f);
        wv = ft * fs + 1e-10f;
    }
    g_w16[((size_t)u * S_ + i) * S_ + j] = __float2half(wv);

    red[j] = wv;
    __syncthreads();
    for (int off = 128; off > 0; off >>= 1) {
        if (j < off) red[j] += red[j + off];
        __syncthreads();
    }
    if (j == 0) g_den[u * S_ + i] = red[0];
}

__global__ void k_hfinal(float* __restrict__ dst)
{
    int i = blockIdx.x * blockDim.x + threadIdx.x;
    if (i < U_ * H_) dst[i] = g_hfin[i];
}

/* ------------------------------------------------------------------ */
extern "C" void kernel_launch(void* const* d_in, const int* in_sizes, int n_in,
                              void* d_out, int out_size)
{
    const int*   x        = (const int*)  d_in[0];
    const float* t        = (const float*)d_in[1];
    const int*   t_slot   = (const int*)  d_in[2];
    const float* s        = (const float*)d_in[3];
    const int*   y_t_slot = (const int*)  d_in[5];
    const float* h0       = (const float*)d_in[7];
    const int*   act_user = (const int*)  d_in[8];
    const int*   wm       = (const int*)  d_in[9];
    const float* wwi      = (const float*)d_in[10];
    const float* sigma    = (const float*)d_in[11];
    const float* enc_w    = (const float*)d_in[12];
    const float* user_w   = (const float*)d_in[13];
    const float* wenc     = (const float*)d_in[14];
    const float* fcpt_w   = (const float*)d_in[15];
    const float* fcpt_b   = (const float*)d_in[16];
    const float* W_ih     = (const float*)d_in[17];
    const float* W_hh     = (const float*)d_in[18];
    const float* b_ih     = (const float*)d_in[19];
    const float* b_hh     = (const float*)d_in[20];
    const float* fc_w     = (const float*)d_in[21];
    const float* fc_b     = (const float*)d_in[22];
    float* out = (float*)d_out;

    void *pT, *pEnch, *pEncl, *pG1h, *pG1l, *pE2, *pTh, *pTl, *pG2h, *pG2l, *pT2;
    void *pUwh, *pUwl, *pP2, *pP3, *pCvec;
    void *pB1h, *pB1l, *pB2h, *pB2l, *pWihh, *pWihl, *pWhh16;
    void *pFcwA16, *pFcwBh, *pFcwBl, *pFcwCh, *pFcwCl;
    void *pOut16, *pHfin, *pW16, *pDen, *pOw16;
    cudaGetSymbolAddress(&pT, g_T);
    cudaGetSymbolAddress(&pEnch, g_ench);  cudaGetSymbolAddress(&pEncl, g_encl);
    cudaGetSymbolAddress(&pG1h, g_G1h);    cudaGetSymbolAddress(&pG1l, g_G1l);
    cudaGetSymbolAddress(&pE2, g_E2);
    cudaGetSymbolAddress(&pTh, g_Th);      cudaGetSymbolAddress(&pTl, g_Tl);
    cudaGetSymbolAddress(&pG2h, g_G2h);    cudaGetSymbolAddress(&pG2l, g_G2l);
    cudaGetSymbolAddress(&pT2, g_T2);
    cudaGetSymbolAddress(&pUwh, g_uwh);    cudaGetSymbolAddress(&pUwl, g_uwl);
    cudaGetSymbolAddress(&pP2, g_P2);      cudaGetSymbolAddress(&pP3, g_P3);
    cudaGetSymbolAddress(&pCvec, g_cvec);
    cudaGetSymbolAddress(&pB1h, g_B1h);    cudaGetSymbolAddress(&pB1l, g_B1l);
    cudaGetSymbolAddress(&pB2h, g_B2h);    cudaGetSymbolAddress(&pB2l, g_B2l);
    cudaGetSymbolAddress(&pWihh, g_wihh);  cudaGetSymbolAddress(&pWihl, g_wihl);
    cudaGetSymbolAddress(&pWhh16, g_whh16);
    cudaGetSymbolAddress(&pFcwA16, g_fcwA16);
    cudaGetSymbolAddress(&pFcwBh, g_fcwBh); cudaGetSymbolAddress(&pFcwBl, g_fcwBl);
    cudaGetSymbolAddress(&pFcwCh, g_fcwCh); cudaGetSymbolAddress(&pFcwCl, g_fcwCl);
    cudaGetSymbolAddress(&pOut16, g_out16); cudaGetSymbolAddress(&pHfin, g_hfin);
    cudaGetSymbolAddress(&pW16, g_w16);    cudaGetSymbolAddress(&pDen, g_den);
    cudaGetSymbolAddress(&pOw16, g_ow16);

    cudaFuncSetAttribute(hmma_gemm_b, cudaFuncAttributeMaxDynamicSharedMemorySize, GEMM_SMEM);
    cudaFuncSetAttribute(hmma_gemm16, cudaFuncAttributeMaxDynamicSharedMemorySize, GEMM16_SMEM);
    cudaFuncSetAttribute(k_att_mma,   cudaFuncAttributeMaxDynamicSharedMemorySize, ATT_SMEM);
    cudaFuncSetAttribute(k_rnn3,      cudaFuncAttributeMaxDynamicSharedMemorySize, RNN3_SMEM);

    /* prep + splits */
    k_week<<<168, 256>>>(sigma, wwi, wm, wenc);
    k_userw<<<128, 512>>>(user_w, act_user);
    k_cvec<<<2, 256>>>(fcpt_b, W_ih, b_ih, b_hh);
    k_split8h<<<64, 256>>>(W_hh, H_, 0, 9, 512, 512, (__half*)pWhh16);
    k_split8<<<512, 256>>>(enc_w,  H_,  0,    9, V_,  VPAD,
                           (__nv_bfloat16*)pEnch, (__nv_bfloat16*)pEncl);
    k_split8<<<64, 256>>>(W_ih,   H_,  0,    9, 512, 512,
                           (__nv_bfloat16*)pWihh, (__nv_bfloat16*)pWihl);
    k_split8<<<32, 256>>>((const float*)pT, H2_, 0, 8, 168, 256,
                           (__nv_bfloat16*)pTh, (__nv_bfloat16*)pTl);
    k_split_t<<<128, 256>>>(fcpt_w, 768, 0,   512,
                            (__nv_bfloat16*)pB1h, (__nv_bfloat16*)pB1l);
    k_split_t<<<64, 256>>>(fcpt_w, 768, 512, 256,
                            (__nv_bfloat16*)pB2h, (__nv_bfloat16*)pB2l);
    k_split8<<<512, 256>>>(fc_w,   1280, 512, 9, V_,  VPAD,
                           (__nv_bfloat16*)pFcwBh, (__nv_bfloat16*)pFcwBl);
    k_split8<<<256, 256>>>(fc_w,   1280, 1024, 8, V_, VPAD,
                           (__nv_bfloat16*)pFcwCh, (__nv_bfloat16*)pFcwCl);
    k_split8h<<<512, 256>>>(fc_w,  1280, 0,   9, V_,  VPAD, (__half*)pFcwA16);

    /* batched small GEMMs: {G1, G2} */
    {
        GemmTask tg1 = { (const __nv_bfloat16*)pWihh, (const __nv_bfloat16*)pWihl,
                         (const __nv_bfloat16*)pB1h,  (const __nv_bfloat16*)pB1l,
                         nullptr, nullptr,
                         (__nv_bfloat16*)pG1h, (__nv_bfloat16*)pG1l, H_, 512, 2 };
        GemmTask tg2 = { (const __nv_bfloat16*)pWihh, (const __nv_bfloat16*)pWihl,
                         (const __nv_bfloat16*)pB2h,  (const __nv_bfloat16*)pB2l,
                         nullptr, nullptr,
                         (__nv_bfloat16*)pG2h, (__nv_bfloat16*)pG2l, H_, 256, 1 };
        hmma_gemm_b<<<12, 256, GEMM_SMEM>>>(tg1, tg2, tg1, tg1, 8, 4, 0, 0);
    }
    /* batched: {E2, T2, P2, P3} — 144 CTAs, one wave */
    {
        GemmTask te2 = { (const __nv_bfloat16*)pEnch, (const __nv_bfloat16*)pEncl,
                         (const __nv_bfloat16*)pG1h,  (const __nv_bfloat16*)pG1l,
                         nullptr, (float*)pE2, nullptr, nullptr, H_, 512, 2 };
        GemmTask tt2 = { (const __nv_bfloat16*)pTh,   (const __nv_bfloat16*)pTl,
                         (const __nv_bfloat16*)pG2h,  (const __nv_bfloat16*)pG2l,
                         (const float*)pCvec, (float*)pT2, nullptr, nullptr, H2_, 512, 2 };
        GemmTask tp2 = { (const __nv_bfloat16*)pUwh,  (const __nv_bfloat16*)pUwl,
                         (const __nv_bfloat16*)pFcwBh, (const __nv_bfloat16*)pFcwBl,
                         nullptr, (float*)pP2, nullptr, nullptr, H_, V_, 20 };
        GemmTask tp3 = { (const __nv_bfloat16*)pTh,   (const __nv_bfloat16*)pTl,
                         (const __nv_bfloat16*)pFcwCh, (const __nv_bfloat16*)pFcwCl,
                         nullptr, (float*)pP3, nullptr, nullptr, H2_, V_, 20 };
        hmma_gemm_b<<<144, 256, GEMM_SMEM>>>(te2, tt2, tp2, tp3, 80, 4, 20, 40);
    }

    /* RNN */
    k_rnn3<<<32, 256, RNN3_SMEM>>>((const float*)pE2, (const float*)pT2,
                                   x, t_slot, (const __half*)pWhh16, h0,
                                   (__half*)pOut16, (float*)pHfin, S_);

    /* attention */
    k_w<<<dim3(S_, U_), 256>>>(t, s);
    k_att_mma<<<dim3(2, 2, U_), 256, ATT_SMEM>>>(
        (const __half*)pW16, (const __half*)pOut16,
        (const float*)pDen, (__half*)pOw16);

    /* final projection */
    hmma_gemm16<<<dim3(VPAD / 256, MSU / 128), 256, GEMM16_SMEM>>>(
        (const __half*)pOw16, (const __half*)pFcwA16,
        fc_b, (const float*)pP2, (const float*)pP3, y_t_slot,
        out, H_, V_);

    size_t yelems = (size_t)S_ * U_ * V_;
    if ((size_t)out_size >= yelems + U_ * H_)
        k_hfinal<<<(U_ * H_ + 255) / 256, 256>>>(out + yelems);
}

// round 15
// speedup vs baseline: 1.1446x; 1.1446x over previous
#include <cuda_runtime.h>
#include <cuda_bf16.h>
#include <cuda_fp16.h>
#include <math.h>
#include <stdint.h>

#define S_  256
#define U_  64
#define H_  512
#define H2_ 256
#define V_  5000
#define MSU 16384
#define VPAD 5120
#define PI_F 3.14159265358979323846f

/* ------------------------- device scratch ------------------------- */
__device__ float         g_T    [168 * H2_];
__device__ __nv_bfloat16 g_ench [(size_t)VPAD * H_];
__device__ __nv_bfloat16 g_encl [(size_t)VPAD * H_];
__device__ __nv_bfloat16 g_G1h  [512 * H_];
__device__ __nv_bfloat16 g_G1l  [512 * H_];
__device__ float         g_E2   [(size_t)VPAD * H_];
__device__ __nv_bfloat16 g_Th   [256 * H2_];
__device__ __nv_bfloat16 g_Tl   [256 * H2_];
__device__ __nv_bfloat16 g_G2h  [512 * H2_];
__device__ __nv_bfloat16 g_G2l  [512 * H2_];
__device__ float         g_T2   [256 * H_];
__device__ __nv_bfloat16 g_uwh  [128 * H_];
__device__ __nv_bfloat16 g_uwl  [128 * H_];
__device__ float         g_P2   [(size_t)128 * V_];
__device__ float         g_P3   [(size_t)256 * V_];
__device__ __nv_bfloat16 g_B1h  [512 * H_];
__device__ __nv_bfloat16 g_B1l  [512 * H_];
__device__ __nv_bfloat16 g_B2h  [256 * H_];
__device__ __nv_bfloat16 g_B2l  [256 * H_];
__device__ __nv_bfloat16 g_wihh [512 * H_];
__device__ __nv_bfloat16 g_wihl [512 * H_];
__device__ __half        g_whh16[512 * H_];
__device__ __half        g_fcwA16[(size_t)VPAD * H_];
__device__ __nv_bfloat16 g_fcwBh[(size_t)VPAD * H_];
__device__ __nv_bfloat16 g_fcwBl[(size_t)VPAD * H_];
__device__ __nv_bfloat16 g_fcwCh[(size_t)VPAD * H2_];
__device__ __nv_bfloat16 g_fcwCl[(size_t)VPAD * H2_];
__device__ float         g_cvec [H_];
__device__ __half        g_out16[(size_t)MSU * H_];
__device__ float         g_hfin [U_ * H_];
__device__ __half        g_w16  [(size_t)U_ * S_ * S_];
__device__ float         g_den  [(size_t)U_ * S_];
__device__ __half        g_ow16 [(size_t)MSU * H_];

/* ---------------------------- helpers ----------------------------- */
__device__ __forceinline__ uint32_t smem_u32(const void* p) {
    uint32_t a;
    asm("{ .reg .u64 t; cvta.to.shared.u64 t, %1; cvt.u32.u64 %0, t; }"
        : "=r"(a) : "l"(p));
    return a;
}
#define CP_ASYNC16(dst, src) \
    asm volatile("cp.async.cg.shared.global [%0], [%1], 16;" :: "r"(dst), "l"(src))
#define CP_COMMIT() asm volatile("cp.async.commit_group;" ::: "memory")
#define CP_WAIT(n)  asm volatile("cp.async.wait_group %0;" :: "n"(n) : "memory")
#define STS32(addr, v) \
    asm volatile("st.shared.b32 [%0], %1;" :: "r"(addr), "r"(v) : "memory")
#define LDSM4(r0, r1, r2, r3, a) \
    asm volatile("ldmatrix.sync.aligned.m8n8.x4.shared.b16 {%0,%1,%2,%3}, [%4];" \
        : "=r"(r0), "=r"(r1), "=r"(r2), "=r"(r3) : "r"(a))
#define LDSM2T(r0, r1, a) \
    asm volatile("ldmatrix.sync.aligned.m8n8.x2.trans.shared.b16 {%0,%1}, [%2];" \
        : "=r"(r0), "=r"(r1) : "r"(a))
#define LDSM4T(r0, r1, r2, r3, a) \
    asm volatile("ldmatrix.sync.aligned.m8n8.x4.trans.shared.b16 {%0,%1,%2,%3}, [%4];" \
        : "=r"(r0), "=r"(r1), "=r"(r2), "=r"(r3) : "r"(a))
#define CLUSTER_ARRIVE() \
    asm volatile("barrier.cluster.arrive.aligned;" ::: "memory")
#define CLUSTER_WAIT() \
    asm volatile("barrier.cluster.wait.aligned;" ::: "memory")
#define CLUSTER_SYNC() do { CLUSTER_ARRIVE(); CLUSTER_WAIT(); } while (0)

__device__ __forceinline__ void st_cluster_b32(uint32_t addr, uint32_t rank, uint32_t v) {
    asm volatile(
        "{ .reg .b32 ra; mapa.shared::cluster.u32 ra, %0, %1; "
        "st.shared::cluster.b32 [ra], %2; }"
        :: "r"(addr), "r"(rank), "r"(v) : "memory");
}
__device__ __forceinline__ float tanh_fast(float v) {
    float r; asm("tanh.approx.f32 %0, %1;" : "=f"(r) : "f"(v)); return r;
}
__device__ __forceinline__ void mma16816(float* c, const uint32_t* a, const uint32_t* b)
{
    asm volatile(
        "mma.sync.aligned.m16n8k16.row.col.f32.bf16.bf16.f32 "
        "{%0,%1,%2,%3}, {%4,%5,%6,%7}, {%8,%9}, {%0,%1,%2,%3};"
        : "+f"(c[0]), "+f"(c[1]), "+f"(c[2]), "+f"(c[3])
        : "r"(a[0]), "r"(a[1]), "r"(a[2]), "r"(a[3]), "r"(b[0]), "r"(b[1]));
}
__device__ __forceinline__ void mma16816h(float* c, const uint32_t* a, const uint32_t* b)
{
    asm volatile(
        "mma.sync.aligned.m16n8k16.row.col.f32.f16.f16.f32 "
        "{%0,%1,%2,%3}, {%4,%5,%6,%7}, {%8,%9}, {%0,%1,%2,%3};"
        : "+f"(c[0]), "+f"(c[1]), "+f"(c[2]), "+f"(c[3])
        : "r"(a[0]), "r"(a[1]), "r"(a[2]), "r"(a[3]), "r"(b[0]), "r"(b[1]));
}
__device__ __forceinline__ void split2(float v, __nv_bfloat16& h, __nv_bfloat16& l)
{
    h = __float2bfloat16(v);
    l = __float2bfloat16(v - __bfloat162float(h));
}

/* -------------- batched split-bf16 HMMA GEMM (3-term) -------------- */
struct GemmTask {
    const __nv_bfloat16 *Ah, *Al, *Bh, *Bl;
    const float* bias1;
    float* Cf;
    __nv_bfloat16 *Ch, *Cl;
    int K, Nreal, nx;
};

#define SWH 40
#define STAGE_B  61440
#define OFF_AL   10240
#define OFF_BH   20480
#define OFF_BL   40960
#define GEMM_SMEM (2 * STAGE_B)

__global__ __launch_bounds__(256, 1)
void hmma_gemm_b(GemmTask t0, GemmTask t1, GemmTask t2, GemmTask t3,
                 int c0, int c1, int c2, int c3)
{
    extern __shared__ char smem[];
    const uint32_t sbase = smem_u32(smem);
    const int tid  = threadIdx.x;

    GemmTask t;
    int lin = blockIdx.x;
    if (lin < c0)                    { t = t0; }
    else if ((lin -= c0) < c1)       { t = t1; }
    else if ((lin -= c1) < c2)       { t = t2; }
    else                             { lin -= c2; t = t3; }
    const int m0 = (lin / t.nx) * 128;
    const int n0 = (lin % t.nx) * 256;
    const __nv_bfloat16* __restrict__ Ah = t.Ah;
    const __nv_bfloat16* __restrict__ Al = t.Al;
    const __nv_bfloat16* __restrict__ Bh = t.Bh;
    const __nv_bfloat16* __restrict__ Bl = t.Bl;
    const int K = t.K, Nreal = t.Nreal;

    const int warp = tid >> 5, lane = tid & 31;
    const int wm = warp >> 2, wn = warp & 3;
    const int g  = lane >> 2, tig = lane & 3;
    const int L = K >> 5;

    const uint32_t aoffc = ((uint32_t)(wm * 64 + (lane & 15)) * SWH) * 2u
                         + (uint32_t)(lane >> 4) * 16u;
    const int sel  = (lane >> 3) & 3;
    const uint32_t boffc = ((uint32_t)(wn * 64 + ((sel & 2) << 2) + (lane & 7)) * SWH) * 2u
                         + (uint32_t)(sel & 1) * 16u;

    float acc[4][8][4];
#pragma unroll
    for (int mi = 0; mi < 4; mi++)
#pragma unroll
        for (int ni = 0; ni < 8; ni++)
#pragma unroll
            for (int q = 0; q < 4; q++) acc[mi][ni][q] = 0.0f;

    auto load_stage = [&](int chunk, int buf) {
        const uint32_t sg = sbase + (uint32_t)buf * STAGE_B;
        const int k0 = chunk << 5;
#pragma unroll 2
        for (int idx = tid; idx < 512; idx += 256) {
            int r = idx >> 2, c = idx & 3;
            uint32_t dsto = (uint32_t)(r * SWH + c * 8) * 2u;
            size_t srco = (size_t)(m0 + r) * K + k0 + c * 8;
            CP_ASYNC16(sg + dsto,            Ah + srco);
            CP_ASYNC16(sg + OFF_AL + dsto,   Al + srco);
        }
#pragma unroll 4
        for (int idx = tid; idx < 1024; idx += 256) {
            int r = idx >> 2, c = idx & 3;
            uint32_t dsto = (uint32_t)(r * SWH + c * 8) * 2u;
            size_t srco = (size_t)(n0 + r) * K + k0 + c * 8;
            CP_ASYNC16(sg + OFF_BH + dsto,   Bh + srco);
            CP_ASYNC16(sg + OFF_BL + dsto,   Bl + srco);
        }
        CP_COMMIT();
    };

    load_stage(0, 0);

    for (int i = 0; i < L; i++) {
        if (i + 1 < L) { load_stage(i + 1, (i + 1) & 1); CP_WAIT(1); }
        else           { CP_WAIT(0); }
        __syncthreads();

        const uint32_t sg = sbase + (uint32_t)(i & 1) * STAGE_B;
#pragma unroll
        for (int ks = 0; ks < 2; ks++) {
            const uint32_t kb = (uint32_t)ks * 32u;
            uint32_t ah[4][4], al[4][4], bb[8][2];
#pragma unroll
            for (int mi = 0; mi < 4; mi++)
                LDSM4(ah[mi][0], ah[mi][1], ah[mi][2], ah[mi][3],
                      sg + kb + aoffc + (uint32_t)mi * (16 * SWH * 2));
#pragma unroll
            for (int n2 = 0; n2 < 4; n2++)
                LDSM4(bb[2*n2][0], bb[2*n2][1], bb[2*n2+1][0], bb[2*n2+1][1],
                      sg + OFF_BH + kb + boffc + (uint32_t)n2 * (16 * SWH * 2));
#pragma unroll
            for (int mi = 0; mi < 4; mi++)
#pragma unroll
                for (int ni = 0; ni < 8; ni++)
                    mma16816(acc[mi][ni], ah[mi], bb[ni]);
#pragma unroll
            for (int mi = 0; mi < 4; mi++)
                LDSM4(al[mi][0], al[mi][1], al[mi][2], al[mi][3],
                      sg + OFF_AL + kb + aoffc + (uint32_t)mi * (16 * SWH * 2));
#pragma unroll
            for (int mi = 0; mi < 4; mi++)
#pragma unroll
                for (int ni = 0; ni < 8; ni++)
                    mma16816(acc[mi][ni], al[mi], bb[ni]);
#pragma unroll
            for (int n2 = 0; n2 < 4; n2++)
                LDSM4(bb[2*n2][0], bb[2*n2][1], bb[2*n2+1][0], bb[2*n2+1][1],
                      sg + OFF_BL + kb + boffc + (uint32_t)n2 * (16 * SWH * 2));
#pragma unroll
            for (int mi = 0; mi < 4; mi++)
#pragma unroll
                for (int ni = 0; ni < 8; ni++)
                    mma16816(acc[mi][ni], ah[mi], bb[ni]);
        }
        __syncthreads();
    }

#pragma unroll
    for (int mi = 0; mi < 4; mi++) {
        const int row0 = m0 + wm * 64 + mi * 16 + g;
#pragma unroll
        for (int ni = 0; ni < 8; ni++) {
            const int n = n0 + wn * 64 + ni * 8 + tig * 2;
#pragma unroll
            for (int q = 0; q < 4; q++) {
                int rr = row0 + ((q >= 2) ? 8 : 0);
                int nn = n + (q & 1);
                if (nn >= Nreal) continue;
                float f = acc[mi][ni][q];
                if (t.bias1) f += t.bias1[nn];
                if (t.Cf) {
                    t.Cf[(size_t)rr * Nreal + nn] = f;
                } else {
                    __nv_bfloat16 hi, lo;
                    split2(f, hi, lo);
                    t.Ch[(size_t)rr * Nreal + nn] = hi;
                    t.Cl[(size_t)rr * Nreal + nn] = lo;
                }
            }
        }
    }
}

/* ----------------- fp16 HMMA GEMM (final projection) --------------- */
#define SWH2      72
#define G16_OFFB  18432
#define G16_STAGE 55296
#define GEMM16_SMEM (2 * G16_STAGE)

__global__ __launch_bounds__(256, 1)
void hmma_gemm16(const __half* __restrict__ A, const __half* __restrict__ B,
                 const float* __restrict__ bias1,
                 const float* __restrict__ add1,
                 const float* __restrict__ add2, const int* __restrict__ idx2,
                 float* __restrict__ Cf, int K, int Nreal)
{
    extern __shared__ char smem[];
    const uint32_t sbase = smem_u32(smem);
    const int tid  = threadIdx.x;
    const int m0   = blockIdx.y * 128;
    const int n0   = blockIdx.x * 256;
    const int warp = tid >> 5, lane = tid & 31;
    const int wm = warp >> 2, wn = warp & 3;
    const int g  = lane >> 2, tig = lane & 3;
    const int L = K >> 6;

    const uint32_t aoffc = ((uint32_t)(wm * 64 + (lane & 15)) * SWH2) * 2u
                         + (uint32_t)(lane >> 4) * 16u;
    const int sel  = (lane >> 3) & 3;
    const uint32_t boffc = ((uint32_t)(wn * 64 + ((sel & 2) << 2) + (lane & 7)) * SWH2) * 2u
                         + (uint32_t)(sel & 1) * 16u;

    float acc[4][8][4];
#pragma unroll
    for (int mi = 0; mi < 4; mi++)
#pragma unroll
        for (int ni = 0; ni < 8; ni++)
#pragma unroll
            for (int q = 0; q < 4; q++) acc[mi][ni][q] = 0.0f;

    auto load_stage = [&](int chunk, int buf) {
        const uint32_t sg = sbase + (uint32_t)buf * G16_STAGE;
        const int k0 = chunk << 6;
#pragma unroll 4
        for (int idx = tid; idx < 1024; idx += 256) {
            int r = idx >> 3, c = idx & 7;
            CP_ASYNC16(sg + (uint32_t)(r * SWH2 + c * 8) * 2u,
                       A + (size_t)(m0 + r) * K + k0 + c * 8);
        }
#pragma unroll 8
        for (int idx = tid; idx < 2048; idx += 256) {
            int r = idx >> 3, c = idx & 7;
            CP_ASYNC16(sg + G16_OFFB + (uint32_t)(r * SWH2 + c * 8) * 2u,
                       B + (size_t)(n0 + r) * K + k0 + c * 8);
        }
        CP_COMMIT();
    };

    load_stage(0, 0);

    for (int i = 0; i < L; i++) {
        if (i + 1 < L) { load_stage(i + 1, (i + 1) & 1); CP_WAIT(1); }
        else           { CP_WAIT(0); }
        __syncthreads();

        const uint32_t sg = sbase + (uint32_t)(i & 1) * G16_STAGE;
#pragma unroll
        for (int ks = 0; ks < 4; ks++) {
            const uint32_t kb = (uint32_t)ks * 32u;
            uint32_t ah[4][4], bb[8][2];
#pragma unroll
            for (int mi = 0; mi < 4; mi++)
                LDSM4(ah[mi][0], ah[mi][1], ah[mi][2], ah[mi][3],
                      sg + kb + aoffc + (uint32_t)mi * (16 * SWH2 * 2));
#pragma unroll
            for (int n2 = 0; n2 < 4; n2++)
                LDSM4(bb[2*n2][0], bb[2*n2][1], bb[2*n2+1][0], bb[2*n2+1][1],
                      sg + G16_OFFB + kb + boffc + (uint32_t)n2 * (16 * SWH2 * 2));
#pragma unroll
            for (int mi = 0; mi < 4; mi++)
#pragma unroll
                for (int ni = 0; ni < 8; ni++)
                    mma16816h(acc[mi][ni], ah[mi], bb[ni]);
        }
        __syncthreads();
    }

#pragma unroll
    for (int mi = 0; mi < 4; mi++) {
        const int row0 = m0 + wm * 64 + mi * 16 + g;
        int i2[2] = { 0, 0 };
        if (add2) { i2[0] = idx2[row0]; i2[1] = idx2[row0 + 8]; }
#pragma unroll
        for (int ni = 0; ni < 8; ni++) {
            const int n = n0 + wn * 64 + ni * 8 + tig * 2;
#pragma unroll
            for (int q = 0; q < 4; q++) {
                int rr = row0 + ((q >= 2) ? 8 : 0);
                int nn = n + (q & 1);
                if (nn >= Nreal) continue;
                float f = acc[mi][ni][q] + bias1[nn]
                        + add1[(size_t)(rr & 63) * Nreal + nn]
                        + add2[(size_t)i2[q >> 1] * Nreal + nn];
                Cf[(size_t)rr * Nreal + nn] = f;
            }
        }
    }
}

/* ------------------------- attention HMMA -------------------------- */
#define ATT_SWA   40
#define ATT_SWB   264
#define ATT_B_OFF (128 * ATT_SWA * 2)
#define ATT_STAGE (ATT_B_OFF + 32 * ATT_SWB * 2)
#define ATT_SMEM  (2 * ATT_STAGE)

__global__ __launch_bounds__(256, 1)
void k_att_mma(const __half* __restrict__ w16, const __half* __restrict__ o16,
               const float* __restrict__ den, __half* __restrict__ ow)
{
    extern __shared__ char smem[];
    const uint32_t sbase = smem_u32(smem);
    const int tid  = threadIdx.x;
    const int u    = blockIdx.z;
    const int i0   = blockIdx.y * 128;
    const int h0   = blockIdx.x * 256;
    const int warp = tid >> 5, lane = tid & 31;
    const int wm = warp >> 2, wn = warp & 3;
    const int g  = lane >> 2, tig = lane & 3;
    const int L  = (i0 + 128) >> 5;

    const uint32_t aoffc = ((uint32_t)(wm * 64 + (lane & 15)) * ATT_SWA) * 2u
                         + (uint32_t)(lane >> 4) * 16u;
    const uint32_t boffc = ((uint32_t)((lane & 7) + ((lane >> 3) & 1) * 8) * ATT_SWB) * 2u
                         + (uint32_t)(lane >> 4) * 16u;

    float acc[4][8][4];
#pragma unroll
    for (int mi = 0; mi < 4; mi++)
#pragma unroll
        for (int ni = 0; ni < 8; ni++)
#pragma unroll
            for (int q = 0; q < 4; q++) acc[mi][ni][q] = 0.0f;

    auto load_stage = [&](int chunk, int buf) {
        const uint32_t sg = sbase + (uint32_t)buf * ATT_STAGE;
        const int j0 = chunk << 5;
#pragma unroll 2
        for (int idx = tid; idx < 512; idx += 256) {
            int r = idx >> 2, c = idx & 3;
            CP_ASYNC16(sg + (uint32_t)(r * ATT_SWA + c * 8) * 2u,
                       w16 + (size_t)u * (S_ * S_) + (size_t)(i0 + r) * S_ + j0 + c * 8);
        }
#pragma unroll 4
        for (int idx = tid; idx < 1024; idx += 256) {
            int r = idx >> 5, c = idx & 31;
            CP_ASYNC16(sg + ATT_B_OFF + (uint32_t)(r * ATT_SWB + c * 8) * 2u,
                       o16 + ((size_t)(j0 + r) * U_ + u) * H_ + h0 + c * 8);
        }
        CP_COMMIT();
    };

    load_stage(0, 0);

    for (int i = 0; i < L; i++) {
        if (i + 1 < L) { load_stage(i + 1, (i + 1) & 1); CP_WAIT(1); }
        else           { CP_WAIT(0); }
        __syncthreads();

        const uint32_t sg = sbase + (uint32_t)(i & 1) * ATT_STAGE;
#pragma unroll
        for (int ks = 0; ks < 2; ks++) {
            uint32_t ah[4][4], bb[8][2];
#pragma unroll
            for (int mi = 0; mi < 4; mi++)
                LDSM4(ah[mi][0], ah[mi][1], ah[mi][2], ah[mi][3],
                      sg + (uint32_t)ks * 32u + aoffc + (uint32_t)mi * (16 * ATT_SWA * 2));
#pragma unroll
            for (int n2 = 0; n2 < 4; n2++)
                LDSM4T(bb[2*n2][0], bb[2*n2][1], bb[2*n2+1][0], bb[2*n2+1][1],
                       sg + ATT_B_OFF + (uint32_t)ks * (16 * ATT_SWB * 2) + boffc
                          + (uint32_t)(wn * 64 + n2 * 16) * 2u);
#pragma unroll
            for (int mi = 0; mi < 4; mi++)
#pragma unroll
                for (int ni = 0; ni < 8; ni++)
                    mma16816h(acc[mi][ni], ah[mi], bb[ni]);
        }
        __syncthreads();
    }

#pragma unroll
    for (int mi = 0; mi < 4; mi++) {
        const int ia = i0 + wm * 64 + mi * 16 + g;
        const float d0 = 1.0f / den[u * S_ + ia];
        const float d1 = 1.0f / den[u * S_ + ia + 8];
#pragma unroll
        for (int ni = 0; ni < 8; ni++) {
            const int h = h0 + wn * 64 + ni * 8 + tig * 2;
            uint32_t p0 = (uint32_t)__half_as_ushort(__float2half(acc[mi][ni][0] * d0))
                        | ((uint32_t)__half_as_ushort(__float2half(acc[mi][ni][1] * d0)) << 16);
            uint32_t p1 = (uint32_t)__half_as_ushort(__float2half(acc[mi][ni][2] * d1))
                        | ((uint32_t)__half_as_ushort(__float2half(acc[mi][ni][3] * d1)) << 16);
            ((uint32_t*)ow)[(((size_t)ia      * U_ + u) * H_ + h) >> 1] = p0;
            ((uint32_t*)ow)[(((size_t)(ia + 8)* U_ + u) * H_ + h) >> 1] = p1;
        }
    }
}

/* ----------------------- vectorized splits ------------------------- */
__global__ __launch_bounds__(256)
void k_split8(const float* __restrict__ src, int pitch, int col0, int lcols,
              int rows, int padRows,
              __nv_bfloat16* __restrict__ dh, __nv_bfloat16* __restrict__ dl)
{
    const int cmask = (1 << lcols) - 1;
    const size_t total8 = ((size_t)padRows << lcols) >> 3;
    for (size_t gidx = (size_t)blockIdx.x * blockDim.x + threadIdx.x;
         gidx < total8; gidx += (size_t)gridDim.x * blockDim.x) {
        size_t idx = gidx << 3;
        int r = (int)(idx >> lcols);
        int c = (int)idx & cmask;
        float4 v0, v1;
        if (r < rows) {
            const float* p = src + (size_t)r * pitch + col0 + c;
            v0 = *(const float4*)p;
            v1 = *(const float4*)(p + 4);
        } else {
            v0 = make_float4(0.f, 0.f, 0.f, 0.f);
            v1 = v0;
        }
        float vv[8] = { v0.x, v0.y, v0.z, v0.w, v1.x, v1.y, v1.z, v1.w };
        uint32_t hp[4], lp[4];
#pragma unroll
        for (int i = 0; i < 4; i++) {
            __nv_bfloat16 h0, l0, h1, l1;
            split2(vv[2 * i],     h0, l0);
            split2(vv[2 * i + 1], h1, l1);
            hp[i] = (uint32_t)*(uint16_t*)&h0 | ((uint32_t)*(uint16_t*)&h1 << 16);
            lp[i] = (uint32_t)*(uint16_t*)&l0 | ((uint32_t)*(uint16_t*)&l1 << 16);
        }
        *(uint4*)(dh + idx) = make_uint4(hp[0], hp[1], hp[2], hp[3]);
        *(uint4*)(dl + idx) = make_uint4(lp[0], lp[1], lp[2], lp[3]);
    }
}

__global__ __launch_bounds__(256)
void k_split8h(const float* __restrict__ src, int pitch, int col0, int lcols,
               int rows, int padRows, __half* __restrict__ d)
{
    const int cmask = (1 << lcols) - 1;
    const size_t total8 = ((size_t)padRows << lcols) >> 3;
    for (size_t gidx = (size_t)blockIdx.x * blockDim.x + threadIdx.x;
         gidx < total8; gidx += (size_t)gridDim.x * blockDim.x) {
        size_t idx = gidx << 3;
        int r = (int)(idx >> lcols);
        int c = (int)idx & cmask;
        float4 v0, v1;
        if (r < rows) {
            const float* p = src + (size_t)r * pitch + col0 + c;
            v0 = *(const float4*)p;
            v1 = *(const float4*)(p + 4);
        } else {
            v0 = make_float4(0.f, 0.f, 0.f, 0.f);
            v1 = v0;
        }
        float vv[8] = { v0.x, v0.y, v0.z, v0.w, v1.x, v1.y, v1.z, v1.w };
        uint32_t hp[4];
#pragma unroll
        for (int i = 0; i < 4; i++) {
            __half a = __float2half(vv[2 * i]);
            __half b = __float2half(vv[2 * i + 1]);
            hp[i] = (uint32_t)__half_as_ushort(a) | ((uint32_t)__half_as_ushort(b) << 16);
        }
        *(uint4*)(d + idx) = make_uint4(hp[0], hp[1], hp[2], hp[3]);
    }
}

/* transpose-split */
__global__ __launch_bounds__(256)
void k_split_t(const float* __restrict__ src, int pitch, int col0, int crows,
               __nv_bfloat16* __restrict__ dh, __nv_bfloat16* __restrict__ dl)
{
    const size_t total = (size_t)crows << 9;
    for (size_t idx = (size_t)blockIdx.x * blockDim.x + threadIdx.x;
         idx < total; idx += (size_t)gridDim.x * blockDim.x) {
        int c = (int)(idx >> 9);
        int o = (int)idx & 511;
        float v = src[(size_t)o * pitch + col0 + c];
        __nv_bfloat16 hi, lo;
        split2(v, hi, lo);
        dh[idx] = hi; dl[idx] = lo;
    }
}

/* ----------------------------- misc -------------------------------- */
__global__ void k_userw(const float* __restrict__ user_w, const int* __restrict__ au)
{
    const int u = blockIdx.x;
    const int c = threadIdx.x;
    float v = 0.0f;
    if (u < U_) v = user_w[(size_t)au[u] * H_ + c];
    __nv_bfloat16 hi, lo;
    split2(v, hi, lo);
    g_uwh[u * H_ + c] = hi;
    g_uwl[u * H_ + c] = lo;
}

__global__ void k_cvec(const float* __restrict__ fcpt_b, const float* __restrict__ W_ih,
                       const float* __restrict__ b_ih, const float* __restrict__ b_hh)
{
    const int n = blockIdx.x * blockDim.x + threadIdx.x;
    if (n >= H_) return;
    float a = b_ih[n] + b_hh[n];
    for (int k = 0; k < H_; k++) a += fcpt_b[k] * W_ih[(size_t)n * H_ + k];
    g_cvec[n] = a;
}

__global__ void k_week(const float* __restrict__ sigma,
                       const float* __restrict__ wwi,
                       const int*   __restrict__ wm,
                       const float* __restrict__ wenc)
{
    const int slot = blockIdx.x;
    const int tid  = threadIdx.x;
    __shared__ float ww[168];
    __shared__ float red[256];

    float sig    = fabsf(sigma[slot]);
    float inv2s2 = 1.0f / (2.0f * sig * sig);
    float coef   = rsqrtf(2.0f * PI_F * sig * sig);

    float v = 0.0f;
    if (tid < 168) {
        float x = wwi[slot * 168 + tid];
        v = coef * expf(-x * x * inv2s2);
        ww[tid] = v;
    }
    red[tid] = v;
    __syncthreads();
    for (int off = 128; off > 0; off >>= 1) {
        if (tid < off) red[tid] += red[tid + off];
        __syncthreads();
    }
    const float inv = 1.0f / red[0];

    float acc = 0.0f;
    for (int k = 0; k < 168; k++) {
        int row = wm[slot * 168 + k];
        acc += (ww[k] * inv) * wenc[row * H2_ + tid];
    }
    g_T[slot * H2_ + tid] = acc;
}

/* --------- RNN v5: cluster(4) barrier.cluster + 4 MMA chains -------- */
#define RWPAD 520
#define R3_WST  0
#define R3_HB0  133120
#define R3_HB1  141312
#define RNN3_SMEM 149504

__global__ __cluster_dims__(4, 1, 1) __launch_bounds__(256, 1)
void k_rnn3(const float* __restrict__ E2, const float* __restrict__ T2,
            const int* __restrict__ x, const int* __restrict__ ts,
            const __half* __restrict__ Whh16, const float* __restrict__ h0,
            __half* __restrict__ out16, float* __restrict__ hfin, int steps)
{
    extern __shared__ char sm[];
    const uint32_t sb = smem_u32(sm);
    const int tid = threadIdx.x;
    const int warp = tid >> 5, lane = tid & 31;
    const int ug = blockIdx.x >> 2;
    uint32_t rank;
    asm("mov.u32 %0, %%cluster_ctarank;" : "=r"(rank));
    const int row0 = (int)rank * 128;

    /* stage W rows [row0, row0+128) via vectorized fp16 copies */
    __half* wst = (__half*)(sm + R3_WST);
    for (int idx = tid; idx < 128 * 64; idx += 256) {
        int r = idx >> 6, c8 = (idx & 63) << 3;
        uint4 v = *(const uint4*)&Whh16[(size_t)(row0 + r) * H_ + c8];
        *(uint4*)&wst[r * RWPAD + c8] = v;
    }
    __syncthreads();

    uint32_t A[32][4];
    {
        const uint32_t la = (uint32_t)(lane & 15) * (RWPAD * 2)
                          + (uint32_t)(lane >> 4) * 16u;
        const uint32_t wbase = sb + R3_WST + (uint32_t)warp * 16u * (RWPAD * 2);
#pragma unroll
        for (int kt = 0; kt < 32; kt++)
            LDSM4(A[kt][0], A[kt][1], A[kt][2], A[kt][3],
                  wbase + la + (uint32_t)kt * 32u);
    }

    __half* hb0p = (__half*)(sm + R3_HB0);
    for (int idx = tid; idx < 512 * 8; idx += 256) {
        int k = idx >> 3, u = idx & 7;
        hb0p[k * 8 + u] = __float2half(h0[(size_t)(ug * 8 + u) * H_ + k]);
    }
    __syncthreads();
    CLUSTER_SYNC();

    const int g = lane >> 2, tig = lane & 3;
    const int kr0 = row0 + warp * 16 + g;
    const int u0 = ug * 8 + tig * 2;
    const uint32_t lb16 = (uint32_t)(lane & 15) * 16u;

    float pv[4];
    {
        int xa = __ldg(x + u0), xb = __ldg(x + u0 + 1);
        int ta = __ldg(ts + u0), tb = __ldg(ts + u0 + 1);
        pv[0] = __ldg(E2 + (size_t)xa * H_ + kr0)     + __ldg(T2 + (size_t)ta * H_ + kr0);
        pv[1] = __ldg(E2 + (size_t)xb * H_ + kr0)     + __ldg(T2 + (size_t)tb * H_ + kr0);
        pv[2] = __ldg(E2 + (size_t)xa * H_ + kr0 + 8) + __ldg(T2 + (size_t)ta * H_ + kr0 + 8);
        pv[3] = __ldg(E2 + (size_t)xb * H_ + kr0 + 8) + __ldg(T2 + (size_t)tb * H_ + kr0 + 8);
    }

    for (int s = 0; s < steps; s++) {
        const uint32_t hb = sb + ((s & 1) ? R3_HB1 : R3_HB0);

        /* 4 independent MMA chains of depth 8 */
        float a0[4] = {0.f,0.f,0.f,0.f}, a1[4] = {0.f,0.f,0.f,0.f};
        float a2[4] = {0.f,0.f,0.f,0.f}, a3[4] = {0.f,0.f,0.f,0.f};
#pragma unroll
        for (int kt = 0; kt < 32; kt += 4) {
            uint32_t b0[2], b1[2], b2[2], b3[2];
            LDSM2T(b0[0], b0[1], hb + (uint32_t)((kt + 0) * 16) * 16u + lb16);
            LDSM2T(b1[0], b1[1], hb + (uint32_t)((kt + 1) * 16) * 16u + lb16);
            LDSM2T(b2[0], b2[1], hb + (uint32_t)((kt + 2) * 16) * 16u + lb16);
            LDSM2T(b3[0], b3[1], hb + (uint32_t)((kt + 3) * 16) * 16u + lb16);
            mma16816h(a0, A[kt + 0], b0);
            mma16816h(a1, A[kt + 1], b1);
            mma16816h(a2, A[kt + 2], b2);
            mma16816h(a3, A[kt + 3], b3);
        }
        float acc[4];
#pragma unroll
        for (int q = 0; q < 4; q++) acc[q] = (a0[q] + a1[q]) + (a2[q] + a3[q]);

        float hv0 = tanh_fast(pv[0] + acc[0]);
        float hv1 = tanh_fast(pv[1] + acc[1]);
        float hv2 = tanh_fast(pv[2] + acc[2]);
        float hv3 = tanh_fast(pv[3] + acc[3]);

        const size_t ob = (size_t)s * U_ * H_;
        if (s == steps - 1) {
            out16[ob + (size_t)u0 * H_ + kr0]           = __float2half(hv0);
            out16[ob + (size_t)(u0 + 1) * H_ + kr0]     = __float2half(hv1);
            out16[ob + (size_t)u0 * H_ + kr0 + 8]       = __float2half(hv2);
            out16[ob + (size_t)(u0 + 1) * H_ + kr0 + 8] = __float2half(hv3);
            hfin[(size_t)u0 * H_ + kr0]           = hv0;
            hfin[(size_t)(u0 + 1) * H_ + kr0]     = hv1;
            hfin[(size_t)u0 * H_ + kr0 + 8]       = hv2;
            hfin[(size_t)(u0 + 1) * H_ + kr0 + 8] = hv3;
        } else {
            uint32_t p0 = (uint32_t)__half_as_ushort(__float2half(hv0))
                        | ((uint32_t)__half_as_ushort(__float2half(hv1)) << 16);
            uint32_t p1 = (uint32_t)__half_as_ushort(__float2half(hv2))
                        | ((uint32_t)__half_as_ushort(__float2half(hv3)) << 16);
            const uint32_t nbo = ((s & 1) ? R3_HB0 : R3_HB1);
            uint32_t d0 = sb + nbo + (uint32_t)(kr0 * 8 + tig * 2) * 2u;
            uint32_t d1 = sb + nbo + (uint32_t)((kr0 + 8) * 8 + tig * 2) * 2u;
#pragma unroll
            for (int r = 0; r < 4; r++) {
                if ((uint32_t)r == rank) { STS32(d0, p0); STS32(d1, p1); }
                else {
                    st_cluster_b32(d0, (uint32_t)r, p0);
                    st_cluster_b32(d1, (uint32_t)r, p1);
                }
            }
            CLUSTER_ARRIVE();
            /* off-critical-path work inside the barrier window */
            out16[ob + (size_t)u0 * H_ + kr0]           = __float2half(hv0);
            out16[ob + (size_t)(u0 + 1) * H_ + kr0]     = __float2half(hv1);
            out16[ob + (size_t)u0 * H_ + kr0 + 8]       = __float2half(hv2);
            out16[ob + (size_t)(u0 + 1) * H_ + kr0 + 8] = __float2half(hv3);
            const int s1o = (s + 1) * U_;
            int xa = __ldg(x + s1o + u0), xb = __ldg(x + s1o + u0 + 1);
            int ta = __ldg(ts + s1o + u0), tb = __ldg(ts + s1o + u0 + 1);
            float n0 = __ldg(E2 + (size_t)xa * H_ + kr0)     + __ldg(T2 + (size_t)ta * H_ + kr0);
            float n1 = __ldg(E2 + (size_t)xb * H_ + kr0)     + __ldg(T2 + (size_t)tb * H_ + kr0);
            float n2 = __ldg(E2 + (size_t)xa * H_ + kr0 + 8) + __ldg(T2 + (size_t)ta * H_ + kr0 + 8);
            float n3 = __ldg(E2 + (size_t)xb * H_ + kr0 + 8) + __ldg(T2 + (size_t)tb * H_ + kr0 + 8);
            CLUSTER_WAIT();
            pv[0] = n0; pv[1] = n1; pv[2] = n2; pv[3] = n3;
        }
    }
}

/* ------------------- attention weights + den ----------------------- */
__global__ void k_w(const float* __restrict__ t, const float* __restrict__ s)
{
    const int i = blockIdx.x, u = blockIdx.y;
    const int j = threadIdx.x;
    __shared__ float red[256];

    float wv = 0.0f;
    if (j <= i) {
        float dt = t[i * U_ + u] - t[j * U_ + u];
        float d0 = s[((size_t)i * U_ + u) * 2 + 0] - s[((size_t)j * U_ + u) * 2 + 0];
        float d1 = s[((size_t)i * U_ + u) * 2 + 1] - s[((size_t)j * U_ + u) * 2 + 1];
        float ds = sqrtf(d0 * d0 + d1 * d1);
        float ft = (cosf(dt * (2.0f * PI_F / 86400.0f)) + 1.0f) * 0.5f
                 * expf(-(dt / 86400.0f) * 0.1f);
        float fs = expf(-ds * 100.0f);
        wv = ft * fs + 1e-10f;
    }
    g_w16[((size_t)u * S_ + i) * S_ + j] = __float2half(wv);

    red[j] = wv;
    __syncthreads();
    for (int off = 128; off > 0; off >>= 1) {
        if (j < off) red[j] += red[j + off];
        __syncthreads();
    }
    if (j == 0) g_den[u * S_ + i] = red[0];
}

__global__ void k_hfinal(float* __restrict__ dst)
{
    int i = blockIdx.x * blockDim.x + threadIdx.x;
    if (i < U_ * H_) dst[i] = g_hfin[i];
}

/* ------------------------------------------------------------------ */
extern "C" void kernel_launch(void* const* d_in, const int* in_sizes, int n_in,
                              void* d_out, int out_size)
{
    const int*   x        = (const int*)  d_in[0];
    const float* t        = (const float*)d_in[1];
    const int*   t_slot   = (const int*)  d_in[2];
    const float* s        = (const float*)d_in[3];
    const int*   y_t_slot = (const int*)  d_in[5];
    const float* h0       = (const float*)d_in[7];
    const int*   act_user = (const int*)  d_in[8];
    const int*   wm       = (const int*)  d_in[9];
    const float* wwi      = (const float*)d_in[10];
    const float* sigma    = (const float*)d_in[11];
    const float* enc_w    = (const float*)d_in[12];
    const float* user_w   = (const float*)d_in[13];
    const float* wenc     = (const float*)d_in[14];
    const float* fcpt_w   = (const float*)d_in[15];
    const float* fcpt_b   = (const float*)d_in[16];
    const float* W_ih     = (const float*)d_in[17];
    const float* W_hh     = (const float*)d_in[18];
    const float* b_ih     = (const float*)d_in[19];
    const float* b_hh     = (const float*)d_in[20];
    const float* fc_w     = (const float*)d_in[21];
    const float* fc_b     = (const float*)d_in[22];
    float* out = (float*)d_out;

    void *pT, *pEnch, *pEncl, *pG1h, *pG1l, *pE2, *pTh, *pTl, *pG2h, *pG2l, *pT2;
    void *pUwh, *pUwl, *pP2, *pP3, *pCvec;
    void *pB1h, *pB1l, *pB2h, *pB2l, *pWihh, *pWihl, *pWhh16;
    void *pFcwA16, *pFcwBh, *pFcwBl, *pFcwCh, *pFcwCl;
    void *pOut16, *pHfin, *pW16, *pDen, *pOw16;
    cudaGetSymbolAddress(&pT, g_T);
    cudaGetSymbolAddress(&pEnch, g_ench);  cudaGetSymbolAddress(&pEncl, g_encl);
    cudaGetSymbolAddress(&pG1h, g_G1h);    cudaGetSymbolAddress(&pG1l, g_G1l);
    cudaGetSymbolAddress(&pE2, g_E2);
    cudaGetSymbolAddress(&pTh, g_Th);      cudaGetSymbolAddress(&pTl, g_Tl);
    cudaGetSymbolAddress(&pG2h, g_G2h);    cudaGetSymbolAddress(&pG2l, g_G2l);
    cudaGetSymbolAddress(&pT2, g_T2);
    cudaGetSymbolAddress(&pUwh, g_uwh);    cudaGetSymbolAddress(&pUwl, g_uwl);
    cudaGetSymbolAddress(&pP2, g_P2);      cudaGetSymbolAddress(&pP3, g_P3);
    cudaGetSymbolAddress(&pCvec, g_cvec);
    cudaGetSymbolAddress(&pB1h, g_B1h);    cudaGetSymbolAddress(&pB1l, g_B1l);
    cudaGetSymbolAddress(&pB2h, g_B2h);    cudaGetSymbolAddress(&pB2l, g_B2l);
    cudaGetSymbolAddress(&pWihh, g_wihh);  cudaGetSymbolAddress(&pWihl, g_wihl);
    cudaGetSymbolAddress(&pWhh16, g_whh16);
    cudaGetSymbolAddress(&pFcwA16, g_fcwA16);
    cudaGetSymbolAddress(&pFcwBh, g_fcwBh); cudaGetSymbolAddress(&pFcwBl, g_fcwBl);
    cudaGetSymbolAddress(&pFcwCh, g_fcwCh); cudaGetSymbolAddress(&pFcwCl, g_fcwCl);
    cudaGetSymbolAddress(&pOut16, g_out16); cudaGetSymbolAddress(&pHfin, g_hfin);
    cudaGetSymbolAddress(&pW16, g_w16);    cudaGetSymbolAddress(&pDen, g_den);
    cudaGetSymbolAddress(&pOw16, g_ow16);

    cudaFuncSetAttribute(hmma_gemm_b, cudaFuncAttributeMaxDynamicSharedMemorySize, GEMM_SMEM);
    cudaFuncSetAttribute(hmma_gemm16, cudaFuncAttributeMaxDynamicSharedMemorySize, GEMM16_SMEM);
    cudaFuncSetAttribute(k_att_mma,   cudaFuncAttributeMaxDynamicSharedMemorySize, ATT_SMEM);
    cudaFuncSetAttribute(k_rnn3,      cudaFuncAttributeMaxDynamicSharedMemorySize, RNN3_SMEM);

    /* prep + splits */
    k_week<<<168, 256>>>(sigma, wwi, wm, wenc);
    k_userw<<<128, 512>>>(user_w, act_user);
    k_cvec<<<2, 256>>>(fcpt_b, W_ih, b_ih, b_hh);
    k_split8h<<<64, 256>>>(W_hh, H_, 0, 9, 512, 512, (__half*)pWhh16);
    k_split8<<<512, 256>>>(enc_w,  H_,  0,    9, V_,  VPAD,
                           (__nv_bfloat16*)pEnch, (__nv_bfloat16*)pEncl);
    k_split8<<<64, 256>>>(W_ih,   H_,  0,    9, 512, 512,
                           (__nv_bfloat16*)pWihh, (__nv_bfloat16*)pWihl);
    k_split8<<<32, 256>>>((const float*)pT, H2_, 0, 8, 168, 256,
                           (__nv_bfloat16*)pTh, (__nv_bfloat16*)pTl);
    k_split_t<<<128, 256>>>(fcpt_w, 768, 0,   512,
                            (__nv_bfloat16*)pB1h, (__nv_bfloat16*)pB1l);
    k_split_t<<<64, 256>>>(fcpt_w, 768, 512, 256,
                            (__nv_bfloat16*)pB2h, (__nv_bfloat16*)pB2l);
    k_split8<<<512, 256>>>(fc_w,   1280, 512, 9, V_,  VPAD,
                           (__nv_bfloat16*)pFcwBh, (__nv_bfloat16*)pFcwBl);
    k_split8<<<256, 256>>>(fc_w,   1280, 1024, 8, V_, VPAD,
                           (__nv_bfloat16*)pFcwCh, (__nv_bfloat16*)pFcwCl);
    k_split8h<<<512, 256>>>(fc_w,  1280, 0,   9, V_,  VPAD, (__half*)pFcwA16);

    /* batched small GEMMs: {G1, G2} */
    {
        GemmTask tg1 = { (const __nv_bfloat16*)pWihh, (const __nv_bfloat16*)pWihl,
                         (const __nv_bfloat16*)pB1h,  (const __nv_bfloat16*)pB1l,
                         nullptr, nullptr,
                         (__nv_bfloat16*)pG1h, (__nv_bfloat16*)pG1l, H_, 512, 2 };
        GemmTask tg2 = { (const __nv_bfloat16*)pWihh, (const __nv_bfloat16*)pWihl,
                         (const __nv_bfloat16*)pB2h,  (const __nv_bfloat16*)pB2l,
                         nullptr, nullptr,
                         (__nv_bfloat16*)pG2h, (__nv_bfloat16*)pG2l, H_, 256, 1 };
        hmma_gemm_b<<<12, 256, GEMM_SMEM>>>(tg1, tg2, tg1, tg1, 8, 4, 0, 0);
    }
    /* batched: {E2, T2, P2, P3} — 144 CTAs, one wave */
    {
        GemmTask te2 = { (const __nv_bfloat16*)pEnch, (const __nv_bfloat16*)pEncl,
                         (const __nv_bfloat16*)pG1h,  (const __nv_bfloat16*)pG1l,
                         nullptr, (float*)pE2, nullptr, nullptr, H_, 512, 2 };
        GemmTask tt2 = { (const __nv_bfloat16*)pTh,   (const __nv_bfloat16*)pTl,
                         (const __nv_bfloat16*)pG2h,  (const __nv_bfloat16*)pG2l,
                         (const float*)pCvec, (float*)pT2, nullptr, nullptr, H2_, 512, 2 };
        GemmTask tp2 = { (const __nv_bfloat16*)pUwh,  (const __nv_bfloat16*)pUwl,
                         (const __nv_bfloat16*)pFcwBh, (const __nv_bfloat16*)pFcwBl,
                         nullptr, (float*)pP2, nullptr, nullptr, H_, V_, 20 };
        GemmTask tp3 = { (const __nv_bfloat16*)pTh,   (const __nv_bfloat16*)pTl,
                         (const __nv_bfloat16*)pFcwCh, (const __nv_bfloat16*)pFcwCl,
                         nullptr, (float*)pP3, nullptr, nullptr, H2_, V_, 20 };
        hmma_gemm_b<<<144, 256, GEMM_SMEM>>>(te2, tt2, tp2, tp3, 80, 4, 20, 40);
    }

    /* RNN */
    k_rnn3<<<32, 256, RNN3_SMEM>>>((const float*)pE2, (const float*)pT2,
                                   x, t_slot, (const __half*)pWhh16, h0,
                                   (__half*)pOut16, (float*)pHfin, S_);

    /* attention */
    k_w<<<dim3(S_, U_), 256>>>(t, s);
    k_att_mma<<<dim3(2, 2, U_), 256, ATT_SMEM>>>(
        (const __half*)pW16, (const __half*)pOut16,
        (const float*)pDen, (__half*)pOw16);

    /* final projection */
    hmma_gemm16<<<dim3(VPAD / 256, MSU / 128), 256, GEMM16_SMEM>>>(
        (const __half*)pOw16, (const __half*)pFcwA16,
        fc_b, (const float*)pP2, (const float*)pP3, y_t_slot,
        out, H_, V_);

    size_t yelems = (size_t)S_ * U_ * V_;
    if ((size_t)out_size >= yelems + U_ * H_)
        k_hfinal<<<(U_ * H_ + 255) / 256, 256>>>(out + yelems);
}

// round 16
// speedup vs baseline: 1.2103x; 1.0575x over previous
#include <cuda_runtime.h>
#include <cuda_bf16.h>
#include <cuda_fp16.h>
#include <math.h>
#include <stdint.h>

#define S_  256
#define U_  64
#define H_  512
#define H2_ 256
#define V_  5000
#define MSU 16384
#define VPAD 5120
#define PI_F 3.14159265358979323846f

/* ------------------------- device scratch ------------------------- */
__device__ float         g_T    [168 * H2_];
__device__ __nv_bfloat16 g_ench [(size_t)VPAD * H_];
__device__ __nv_bfloat16 g_encl [(size_t)VPAD * H_];
__device__ __nv_bfloat16 g_G1h  [512 * H_];
__device__ __nv_bfloat16 g_G1l  [512 * H_];
__device__ float         g_E2   [(size_t)VPAD * H_];
__device__ __nv_bfloat16 g_Th   [256 * H2_];
__device__ __nv_bfloat16 g_Tl   [256 * H2_];
__device__ __nv_bfloat16 g_G2h  [512 * H2_];
__device__ __nv_bfloat16 g_G2l  [512 * H2_];
__device__ float         g_T2   [256 * H_];
__device__ __nv_bfloat16 g_uwh  [128 * H_];
__device__ __nv_bfloat16 g_uwl  [128 * H_];
__device__ float         g_P2   [(size_t)128 * V_];
__device__ float         g_P3   [(size_t)256 * V_];
__device__ __nv_bfloat16 g_B1h  [512 * H_];
__device__ __nv_bfloat16 g_B1l  [512 * H_];
__device__ __nv_bfloat16 g_B2h  [256 * H_];
__device__ __nv_bfloat16 g_B2l  [256 * H_];
__device__ __nv_bfloat16 g_wihh [512 * H_];
__device__ __nv_bfloat16 g_wihl [512 * H_];
__device__ __half        g_whh16[512 * H_];
__device__ __half        g_fcwA16[(size_t)VPAD * H_];
__device__ __nv_bfloat16 g_fcwBh[(size_t)VPAD * H_];
__device__ __nv_bfloat16 g_fcwBl[(size_t)VPAD * H_];
__device__ __nv_bfloat16 g_fcwCh[(size_t)VPAD * H2_];
__device__ __nv_bfloat16 g_fcwCl[(size_t)VPAD * H2_];
__device__ float         g_cvec [H_];
__device__ __half        g_out16[(size_t)MSU * H_];
__device__ float         g_hfin [U_ * H_];
__device__ __half        g_w16  [(size_t)U_ * S_ * S_];
__device__ float         g_den  [(size_t)U_ * S_];
__device__ __half        g_ow16 [(size_t)MSU * H_];

/* ---------------------------- helpers ----------------------------- */
__device__ __forceinline__ uint32_t smem_u32(const void* p) {
    uint32_t a;
    asm("{ .reg .u64 t; cvta.to.shared.u64 t, %1; cvt.u32.u64 %0, t; }"
        : "=r"(a) : "l"(p));
    return a;
}
#define CP_ASYNC16(dst, src) \
    asm volatile("cp.async.cg.shared.global [%0], [%1], 16;" :: "r"(dst), "l"(src))
#define CP_COMMIT() asm volatile("cp.async.commit_group;" ::: "memory")
#define CP_WAIT(n)  asm volatile("cp.async.wait_group %0;" :: "n"(n) : "memory")
#define STS32(addr, v) \
    asm volatile("st.shared.b32 [%0], %1;" :: "r"(addr), "r"(v) : "memory")
#define LDSM4(r0, r1, r2, r3, a) \
    asm volatile("ldmatrix.sync.aligned.m8n8.x4.shared.b16 {%0,%1,%2,%3}, [%4];" \
        : "=r"(r0), "=r"(r1), "=r"(r2), "=r"(r3) : "r"(a))
#define LDSM2T(r0, r1, a) \
    asm volatile("ldmatrix.sync.aligned.m8n8.x2.trans.shared.b16 {%0,%1}, [%2];" \
        : "=r"(r0), "=r"(r1) : "r"(a))
#define LDSM4T(r0, r1, r2, r3, a) \
    asm volatile("ldmatrix.sync.aligned.m8n8.x4.trans.shared.b16 {%0,%1,%2,%3}, [%4];" \
        : "=r"(r0), "=r"(r1), "=r"(r2), "=r"(r3) : "r"(a))
#define CLUSTER_ARRIVE() \
    asm volatile("barrier.cluster.arrive.aligned;" ::: "memory")
#define CLUSTER_WAIT() \
    asm volatile("barrier.cluster.wait.aligned;" ::: "memory")
#define CLUSTER_SYNC() do { CLUSTER_ARRIVE(); CLUSTER_WAIT(); } while (0)

__device__ __forceinline__ void st_cluster_b32(uint32_t addr, uint32_t rank, uint32_t v) {
    asm volatile(
        "{ .reg .b32 ra; mapa.shared::cluster.u32 ra, %0, %1; "
        "st.shared::cluster.b32 [ra], %2; }"
        :: "r"(addr), "r"(rank), "r"(v) : "memory");
}
__device__ __forceinline__ float tanh_fast(float v) {
    float r; asm("tanh.approx.f32 %0, %1;" : "=f"(r) : "f"(v)); return r;
}
__device__ __forceinline__ void mma16816(float* c, const uint32_t* a, const uint32_t* b)
{
    asm volatile(
        "mma.sync.aligned.m16n8k16.row.col.f32.bf16.bf16.f32 "
        "{%0,%1,%2,%3}, {%4,%5,%6,%7}, {%8,%9}, {%0,%1,%2,%3};"
        : "+f"(c[0]), "+f"(c[1]), "+f"(c[2]), "+f"(c[3])
        : "r"(a[0]), "r"(a[1]), "r"(a[2]), "r"(a[3]), "r"(b[0]), "r"(b[1]));
}
__device__ __forceinline__ void mma16816h(float* c, const uint32_t* a, const uint32_t* b)
{
    asm volatile(
        "mma.sync.aligned.m16n8k16.row.col.f32.f16.f16.f32 "
        "{%0,%1,%2,%3}, {%4,%5,%6,%7}, {%8,%9}, {%0,%1,%2,%3};"
        : "+f"(c[0]), "+f"(c[1]), "+f"(c[2]), "+f"(c[3])
        : "r"(a[0]), "r"(a[1]), "r"(a[2]), "r"(a[3]), "r"(b[0]), "r"(b[1]));
}
__device__ __forceinline__ void split2(float v, __nv_bfloat16& h, __nv_bfloat16& l)
{
    h = __float2bfloat16(v);
    l = __float2bfloat16(v - __bfloat162float(h));
}

/* -------------- batched split-bf16 HMMA GEMM (3-term) -------------- */
struct GemmTask {
    const __nv_bfloat16 *Ah, *Al, *Bh, *Bl;
    const float* bias1;
    float* Cf;
    __nv_bfloat16 *Ch, *Cl;
    int K, Nreal, nx;
};

#define SWH 40
#define STAGE_B  61440
#define OFF_AL   10240
#define OFF_BH   20480
#define OFF_BL   40960
#define GEMM_SMEM (2 * STAGE_B)

__global__ __launch_bounds__(256, 1)
void hmma_gemm_b(GemmTask t0, GemmTask t1, GemmTask t2, GemmTask t3,
                 int c0, int c1, int c2, int c3)
{
    extern __shared__ char smem[];
    const uint32_t sbase = smem_u32(smem);
    const int tid  = threadIdx.x;

    GemmTask t;
    int lin = blockIdx.x;
    if (lin < c0)                    { t = t0; }
    else if ((lin -= c0) < c1)       { t = t1; }
    else if ((lin -= c1) < c2)       { t = t2; }
    else                             { lin -= c2; t = t3; }
    const int m0 = (lin / t.nx) * 128;
    const int n0 = (lin % t.nx) * 256;
    const __nv_bfloat16* __restrict__ Ah = t.Ah;
    const __nv_bfloat16* __restrict__ Al = t.Al;
    const __nv_bfloat16* __restrict__ Bh = t.Bh;
    const __nv_bfloat16* __restrict__ Bl = t.Bl;
    const int K = t.K, Nreal = t.Nreal;

    const int warp = tid >> 5, lane = tid & 31;
    const int wm = warp >> 2, wn = warp & 3;
    const int g  = lane >> 2, tig = lane & 3;
    const int L = K >> 5;

    const uint32_t aoffc = ((uint32_t)(wm * 64 + (lane & 15)) * SWH) * 2u
                         + (uint32_t)(lane >> 4) * 16u;
    const int sel  = (lane >> 3) & 3;
    const uint32_t boffc = ((uint32_t)(wn * 64 + ((sel & 2) << 2) + (lane & 7)) * SWH) * 2u
                         + (uint32_t)(sel & 1) * 16u;

    float acc[4][8][4];
#pragma unroll
    for (int mi = 0; mi < 4; mi++)
#pragma unroll
        for (int ni = 0; ni < 8; ni++)
#pragma unroll
            for (int q = 0; q < 4; q++) acc[mi][ni][q] = 0.0f;

    auto load_stage = [&](int chunk, int buf) {
        const uint32_t sg = sbase + (uint32_t)buf * STAGE_B;
        const int k0 = chunk << 5;
#pragma unroll 2
        for (int idx = tid; idx < 512; idx += 256) {
            int r = idx >> 2, c = idx & 3;
            uint32_t dsto = (uint32_t)(r * SWH + c * 8) * 2u;
            size_t srco = (size_t)(m0 + r) * K + k0 + c * 8;
            CP_ASYNC16(sg + dsto,            Ah + srco);
            CP_ASYNC16(sg + OFF_AL + dsto,   Al + srco);
        }
#pragma unroll 4
        for (int idx = tid; idx < 1024; idx += 256) {
            int r = idx >> 2, c = idx & 3;
            uint32_t dsto = (uint32_t)(r * SWH + c * 8) * 2u;
            size_t srco = (size_t)(n0 + r) * K + k0 + c * 8;
            CP_ASYNC16(sg + OFF_BH + dsto,   Bh + srco);
            CP_ASYNC16(sg + OFF_BL + dsto,   Bl + srco);
        }
        CP_COMMIT();
    };

    load_stage(0, 0);

    for (int i = 0; i < L; i++) {
        if (i + 1 < L) { load_stage(i + 1, (i + 1) & 1); CP_WAIT(1); }
        else           { CP_WAIT(0); }
        __syncthreads();

        const uint32_t sg = sbase + (uint32_t)(i & 1) * STAGE_B;
#pragma unroll
        for (int ks = 0; ks < 2; ks++) {
            const uint32_t kb = (uint32_t)ks * 32u;
            uint32_t ah[4][4], al[4][4], bb[8][2];
#pragma unroll
            for (int mi = 0; mi < 4; mi++)
                LDSM4(ah[mi][0], ah[mi][1], ah[mi][2], ah[mi][3],
                      sg + kb + aoffc + (uint32_t)mi * (16 * SWH * 2));
#pragma unroll
            for (int n2 = 0; n2 < 4; n2++)
                LDSM4(bb[2*n2][0], bb[2*n2][1], bb[2*n2+1][0], bb[2*n2+1][1],
                      sg + OFF_BH + kb + boffc + (uint32_t)n2 * (16 * SWH * 2));
#pragma unroll
            for (int mi = 0; mi < 4; mi++)
#pragma unroll
                for (int ni = 0; ni < 8; ni++)
                    mma16816(acc[mi][ni], ah[mi], bb[ni]);
#pragma unroll
            for (int mi = 0; mi < 4; mi++)
                LDSM4(al[mi][0], al[mi][1], al[mi][2], al[mi][3],
                      sg + OFF_AL + kb + aoffc + (uint32_t)mi * (16 * SWH * 2));
#pragma unroll
            for (int mi = 0; mi < 4; mi++)
#pragma unroll
                for (int ni = 0; ni < 8; ni++)
                    mma16816(acc[mi][ni], al[mi], bb[ni]);
#pragma unroll
            for (int n2 = 0; n2 < 4; n2++)
                LDSM4(bb[2*n2][0], bb[2*n2][1], bb[2*n2+1][0], bb[2*n2+1][1],
                      sg + OFF_BL + kb + boffc + (uint32_t)n2 * (16 * SWH * 2));
#pragma unroll
            for (int mi = 0; mi < 4; mi++)
#pragma unroll
                for (int ni = 0; ni < 8; ni++)
                    mma16816(acc[mi][ni], ah[mi], bb[ni]);
        }
        __syncthreads();
    }

#pragma unroll
    for (int mi = 0; mi < 4; mi++) {
        const int row0 = m0 + wm * 64 + mi * 16 + g;
#pragma unroll
        for (int ni = 0; ni < 8; ni++) {
            const int n = n0 + wn * 64 + ni * 8 + tig * 2;
#pragma unroll
            for (int q = 0; q < 4; q++) {
                int rr = row0 + ((q >= 2) ? 8 : 0);
                int nn = n + (q & 1);
                if (nn >= Nreal) continue;
                float f = acc[mi][ni][q];
                if (t.bias1) f += t.bias1[nn];
                if (t.Cf) {
                    t.Cf[(size_t)rr * Nreal + nn] = f;
                } else {
                    __nv_bfloat16 hi, lo;
                    split2(f, hi, lo);
                    t.Ch[(size_t)rr * Nreal + nn] = hi;
                    t.Cl[(size_t)rr * Nreal + nn] = lo;
                }
            }
        }
    }
}

/* ----------------- fp16 HMMA GEMM (final projection) --------------- */
#define SWH2      72
#define G16_OFFB  18432
#define G16_STAGE 55296
#define GEMM16_SMEM (2 * G16_STAGE)

__global__ __launch_bounds__(256, 1)
void hmma_gemm16(const __half* __restrict__ A, const __half* __restrict__ B,
                 const float* __restrict__ bias1,
                 const float* __restrict__ add1,
                 const float* __restrict__ add2, const int* __restrict__ idx2,
                 float* __restrict__ Cf, int K, int Nreal)
{
    extern __shared__ char smem[];
    const uint32_t sbase = smem_u32(smem);
    const int tid  = threadIdx.x;
    const int m0   = blockIdx.y * 128;
    const int n0   = blockIdx.x * 256;
    const int warp = tid >> 5, lane = tid & 31;
    const int wm = warp >> 2, wn = warp & 3;
    const int g  = lane >> 2, tig = lane & 3;
    const int L = K >> 6;

    const uint32_t aoffc = ((uint32_t)(wm * 64 + (lane & 15)) * SWH2) * 2u
                         + (uint32_t)(lane >> 4) * 16u;
    const int sel  = (lane >> 3) & 3;
    const uint32_t boffc = ((uint32_t)(wn * 64 + ((sel & 2) << 2) + (lane & 7)) * SWH2) * 2u
                         + (uint32_t)(sel & 1) * 16u;

    float acc[4][8][4];
#pragma unroll
    for (int mi = 0; mi < 4; mi++)
#pragma unroll
        for (int ni = 0; ni < 8; ni++)
#pragma unroll
            for (int q = 0; q < 4; q++) acc[mi][ni][q] = 0.0f;

    auto load_stage = [&](int chunk, int buf) {
        const uint32_t sg = sbase + (uint32_t)buf * G16_STAGE;
        const int k0 = chunk << 6;
#pragma unroll 4
        for (int idx = tid; idx < 1024; idx += 256) {
            int r = idx >> 3, c = idx & 7;
            CP_ASYNC16(sg + (uint32_t)(r * SWH2 + c * 8) * 2u,
                       A + (size_t)(m0 + r) * K + k0 + c * 8);
        }
#pragma unroll 8
        for (int idx = tid; idx < 2048; idx += 256) {
            int r = idx >> 3, c = idx & 7;
            CP_ASYNC16(sg + G16_OFFB + (uint32_t)(r * SWH2 + c * 8) * 2u,
                       B + (size_t)(n0 + r) * K + k0 + c * 8);
        }
        CP_COMMIT();
    };

    load_stage(0, 0);

    for (int i = 0; i < L; i++) {
        if (i + 1 < L) { load_stage(i + 1, (i + 1) & 1); CP_WAIT(1); }
        else           { CP_WAIT(0); }
        __syncthreads();

        const uint32_t sg = sbase + (uint32_t)(i & 1) * G16_STAGE;
#pragma unroll
        for (int ks = 0; ks < 4; ks++) {
            const uint32_t kb = (uint32_t)ks * 32u;
            uint32_t ah[4][4], bb[8][2];
#pragma unroll
            for (int mi = 0; mi < 4; mi++)
                LDSM4(ah[mi][0], ah[mi][1], ah[mi][2], ah[mi][3],
                      sg + kb + aoffc + (uint32_t)mi * (16 * SWH2 * 2));
#pragma unroll
            for (int n2 = 0; n2 < 4; n2++)
                LDSM4(bb[2*n2][0], bb[2*n2][1], bb[2*n2+1][0], bb[2*n2+1][1],
                      sg + G16_OFFB + kb + boffc + (uint32_t)n2 * (16 * SWH2 * 2));
#pragma unroll
            for (int mi = 0; mi < 4; mi++)
#pragma unroll
                for (int ni = 0; ni < 8; ni++)
                    mma16816h(acc[mi][ni], ah[mi], bb[ni]);
        }
        __syncthreads();
    }

#pragma unroll
    for (int mi = 0; mi < 4; mi++) {
        const int row0 = m0 + wm * 64 + mi * 16 + g;
        int i2[2] = { 0, 0 };
        if (add2) { i2[0] = idx2[row0]; i2[1] = idx2[row0 + 8]; }
#pragma unroll
        for (int ni = 0; ni < 8; ni++) {
            const int n = n0 + wn * 64 + ni * 8 + tig * 2;
#pragma unroll
            for (int q = 0; q < 4; q++) {
                int rr = row0 + ((q >= 2) ? 8 : 0);
                int nn = n + (q & 1);
                if (nn >= Nreal) continue;
                float f = acc[mi][ni][q] + bias1[nn]
                        + add1[(size_t)(rr & 63) * Nreal + nn]
                        + add2[(size_t)i2[q >> 1] * Nreal + nn];
                Cf[(size_t)rr * Nreal + nn] = f;
            }
        }
    }
}

/* ------------------------- attention HMMA -------------------------- */
#define ATT_SWA   40
#define ATT_SWB   264
#define ATT_B_OFF (128 * ATT_SWA * 2)
#define ATT_STAGE (ATT_B_OFF + 32 * ATT_SWB * 2)
#define ATT_SMEM  (2 * ATT_STAGE)

__global__ __launch_bounds__(256, 1)
void k_att_mma(const __half* __restrict__ w16, const __half* __restrict__ o16,
               const float* __restrict__ den, __half* __restrict__ ow)
{
    extern __shared__ char smem[];
    const uint32_t sbase = smem_u32(smem);
    const int tid  = threadIdx.x;
    const int u    = blockIdx.z;
    const int i0   = blockIdx.y * 128;
    const int h0   = blockIdx.x * 256;
    const int warp = tid >> 5, lane = tid & 31;
    const int wm = warp >> 2, wn = warp & 3;
    const int g  = lane >> 2, tig = lane & 3;
    const int L  = (i0 + 128) >> 5;

    const uint32_t aoffc = ((uint32_t)(wm * 64 + (lane & 15)) * ATT_SWA) * 2u
                         + (uint32_t)(lane >> 4) * 16u;
    const uint32_t boffc = ((uint32_t)((lane & 7) + ((lane >> 3) & 1) * 8) * ATT_SWB) * 2u
                         + (uint32_t)(lane >> 4) * 16u;

    float acc[4][8][4];
#pragma unroll
    for (int mi = 0; mi < 4; mi++)
#pragma unroll
        for (int ni = 0; ni < 8; ni++)
#pragma unroll
            for (int q = 0; q < 4; q++) acc[mi][ni][q] = 0.0f;

    auto load_stage = [&](int chunk, int buf) {
        const uint32_t sg = sbase + (uint32_t)buf * ATT_STAGE;
        const int j0 = chunk << 5;
#pragma unroll 2
        for (int idx = tid; idx < 512; idx += 256) {
            int r = idx >> 2, c = idx & 3;
            CP_ASYNC16(sg + (uint32_t)(r * ATT_SWA + c * 8) * 2u,
                       w16 + (size_t)u * (S_ * S_) + (size_t)(i0 + r) * S_ + j0 + c * 8);
        }
#pragma unroll 4
        for (int idx = tid; idx < 1024; idx += 256) {
            int r = idx >> 5, c = idx & 31;
            CP_ASYNC16(sg + ATT_B_OFF + (uint32_t)(r * ATT_SWB + c * 8) * 2u,
                       o16 + ((size_t)(j0 + r) * U_ + u) * H_ + h0 + c * 8);
        }
        CP_COMMIT();
    };

    load_stage(0, 0);

    for (int i = 0; i < L; i++) {
        if (i + 1 < L) { load_stage(i + 1, (i + 1) & 1); CP_WAIT(1); }
        else           { CP_WAIT(0); }
        __syncthreads();

        const uint32_t sg = sbase + (uint32_t)(i & 1) * ATT_STAGE;
#pragma unroll
        for (int ks = 0; ks < 2; ks++) {
            uint32_t ah[4][4], bb[8][2];
#pragma unroll
            for (int mi = 0; mi < 4; mi++)
                LDSM4(ah[mi][0], ah[mi][1], ah[mi][2], ah[mi][3],
                      sg + (uint32_t)ks * 32u + aoffc + (uint32_t)mi * (16 * ATT_SWA * 2));
#pragma unroll
            for (int n2 = 0; n2 < 4; n2++)
                LDSM4T(bb[2*n2][0], bb[2*n2][1], bb[2*n2+1][0], bb[2*n2+1][1],
                       sg + ATT_B_OFF + (uint32_t)ks * (16 * ATT_SWB * 2) + boffc
                          + (uint32_t)(wn * 64 + n2 * 16) * 2u);
#pragma unroll
            for (int mi = 0; mi < 4; mi++)
#pragma unroll
                for (int ni = 0; ni < 8; ni++)
                    mma16816h(acc[mi][ni], ah[mi], bb[ni]);
        }
        __syncthreads();
    }

#pragma unroll
    for (int mi = 0; mi < 4; mi++) {
        const int ia = i0 + wm * 64 + mi * 16 + g;
        const float d0 = 1.0f / den[u * S_ + ia];
        const float d1 = 1.0f / den[u * S_ + ia + 8];
#pragma unroll
        for (int ni = 0; ni < 8; ni++) {
            const int h = h0 + wn * 64 + ni * 8 + tig * 2;
            uint32_t p0 = (uint32_t)__half_as_ushort(__float2half(acc[mi][ni][0] * d0))
                        | ((uint32_t)__half_as_ushort(__float2half(acc[mi][ni][1] * d0)) << 16);
            uint32_t p1 = (uint32_t)__half_as_ushort(__float2half(acc[mi][ni][2] * d1))
                        | ((uint32_t)__half_as_ushort(__float2half(acc[mi][ni][3] * d1)) << 16);
            ((uint32_t*)ow)[(((size_t)ia      * U_ + u) * H_ + h) >> 1] = p0;
            ((uint32_t*)ow)[(((size_t)(ia + 8)* U_ + u) * H_ + h) >> 1] = p1;
        }
    }
}

/* ----------------------- vectorized splits ------------------------- */
__global__ __launch_bounds__(256)
void k_split8(const float* __restrict__ src, int pitch, int col0, int lcols,
              int rows, int padRows,
              __nv_bfloat16* __restrict__ dh, __nv_bfloat16* __restrict__ dl)
{
    const int cmask = (1 << lcols) - 1;
    const size_t total8 = ((size_t)padRows << lcols) >> 3;
    for (size_t gidx = (size_t)blockIdx.x * blockDim.x + threadIdx.x;
         gidx < total8; gidx += (size_t)gridDim.x * blockDim.x) {
        size_t idx = gidx << 3;
        int r = (int)(idx >> lcols);
        int c = (int)idx & cmask;
        float4 v0, v1;
        if (r < rows) {
            const float* p = src + (size_t)r * pitch + col0 + c;
            v0 = *(const float4*)p;
            v1 = *(const float4*)(p + 4);
        } else {
            v0 = make_float4(0.f, 0.f, 0.f, 0.f);
            v1 = v0;
        }
        float vv[8] = { v0.x, v0.y, v0.z, v0.w, v1.x, v1.y, v1.z, v1.w };
        uint32_t hp[4], lp[4];
#pragma unroll
        for (int i = 0; i < 4; i++) {
            __nv_bfloat16 h0, l0, h1, l1;
            split2(vv[2 * i],     h0, l0);
            split2(vv[2 * i + 1], h1, l1);
            hp[i] = (uint32_t)*(uint16_t*)&h0 | ((uint32_t)*(uint16_t*)&h1 << 16);
            lp[i] = (uint32_t)*(uint16_t*)&l0 | ((uint32_t)*(uint16_t*)&l1 << 16);
        }
        *(uint4*)(dh + idx) = make_uint4(hp[0], hp[1], hp[2], hp[3]);
        *(uint4*)(dl + idx) = make_uint4(lp[0], lp[1], lp[2], lp[3]);
    }
}

__global__ __launch_bounds__(256)
void k_split8h(const float* __restrict__ src, int pitch, int col0, int lcols,
               int rows, int padRows, __half* __restrict__ d)
{
    const int cmask = (1 << lcols) - 1;
    const size_t total8 = ((size_t)padRows << lcols) >> 3;
    for (size_t gidx = (size_t)blockIdx.x * blockDim.x + threadIdx.x;
         gidx < total8; gidx += (size_t)gridDim.x * blockDim.x) {
        size_t idx = gidx << 3;
        int r = (int)(idx >> lcols);
        int c = (int)idx & cmask;
        float4 v0, v1;
        if (r < rows) {
            const float* p = src + (size_t)r * pitch + col0 + c;
            v0 = *(const float4*)p;
            v1 = *(const float4*)(p + 4);
        } else {
            v0 = make_float4(0.f, 0.f, 0.f, 0.f);
            v1 = v0;
        }
        float vv[8] = { v0.x, v0.y, v0.z, v0.w, v1.x, v1.y, v1.z, v1.w };
        uint32_t hp[4];
#pragma unroll
        for (int i = 0; i < 4; i++) {
            __half a = __float2half(vv[2 * i]);
            __half b = __float2half(vv[2 * i + 1]);
            hp[i] = (uint32_t)__half_as_ushort(a) | ((uint32_t)__half_as_ushort(b) << 16);
        }
        *(uint4*)(d + idx) = make_uint4(hp[0], hp[1], hp[2], hp[3]);
    }
}

/* transpose-split */
__global__ __launch_bounds__(256)
void k_split_t(const float* __restrict__ src, int pitch, int col0, int crows,
               __nv_bfloat16* __restrict__ dh, __nv_bfloat16* __restrict__ dl)
{
    const size_t total = (size_t)crows << 9;
    for (size_t idx = (size_t)blockIdx.x * blockDim.x + threadIdx.x;
         idx < total; idx += (size_t)gridDim.x * blockDim.x) {
        int c = (int)(idx >> 9);
        int o = (int)idx & 511;
        float v = src[(size_t)o * pitch + col0 + c];
        __nv_bfloat16 hi, lo;
        split2(v, hi, lo);
        dh[idx] = hi; dl[idx] = lo;
    }
}

/* ----------------------------- misc -------------------------------- */
__global__ void k_userw(const float* __restrict__ user_w, const int* __restrict__ au)
{
    const int u = blockIdx.x;
    const int c = threadIdx.x;
    float v = 0.0f;
    if (u < U_) v = user_w[(size_t)au[u] * H_ + c];
    __nv_bfloat16 hi, lo;
    split2(v, hi, lo);
    g_uwh[u * H_ + c] = hi;
    g_uwl[u * H_ + c] = lo;
}

__global__ void k_cvec(const float* __restrict__ fcpt_b, const float* __restrict__ W_ih,
                       const float* __restrict__ b_ih, const float* __restrict__ b_hh)
{
    const int n = blockIdx.x * blockDim.x + threadIdx.x;
    if (n >= H_) return;
    float a = b_ih[n] + b_hh[n];
    for (int k = 0; k < H_; k++) a += fcpt_b[k] * W_ih[(size_t)n * H_ + k];
    g_cvec[n] = a;
}

__global__ void k_week(const float* __restrict__ sigma,
                       const float* __restrict__ wwi,
                       const int*   __restrict__ wm,
                       const float* __restrict__ wenc)
{
    const int slot = blockIdx.x;
    const int tid  = threadIdx.x;
    __shared__ float ww[168];
    __shared__ float red[256];

    float sig    = fabsf(sigma[slot]);
    float inv2s2 = 1.0f / (2.0f * sig * sig);
    float coef   = rsqrtf(2.0f * PI_F * sig * sig);

    float v = 0.0f;
    if (tid < 168) {
        float x = wwi[slot * 168 + tid];
        v = coef * expf(-x * x * inv2s2);
        ww[tid] = v;
    }
    red[tid] = v;
    __syncthreads();
    for (int off = 128; off > 0; off >>= 1) {
        if (tid < off) red[tid] += red[tid + off];
        __syncthreads();
    }
    const float inv = 1.0f / red[0];

    float acc = 0.0f;
    for (int k = 0; k < 168; k++) {
        int row = wm[slot * 168 + k];
        acc += (ww[k] * inv) * wenc[row * H2_ + tid];
    }
    g_T[slot * H2_ + tid] = acc;
}

/* --- RNN v6: cluster(4) RNN in clusters 0-7 + aux work CTAs 32+ ----- */
#define RWPAD 520
#define R3_WST  0
#define R3_HB0  133120
#define R3_HB1  141312
#define RNN3_SMEM 149504

__global__ __cluster_dims__(4, 1, 1) __launch_bounds__(256, 1)
void k_rnn3(const float* __restrict__ E2, const float* __restrict__ T2,
            const int* __restrict__ x, const int* __restrict__ ts,
            const __half* __restrict__ Whh16, const float* __restrict__ h0,
            __half* __restrict__ out16, float* __restrict__ hfin,
            const float* __restrict__ tt, const float* __restrict__ ss,
            const float* __restrict__ fcw,
            __half* __restrict__ w16o, float* __restrict__ deno,
            __half* __restrict__ fcwA, int steps)
{
    extern __shared__ char sm[];
    const uint32_t sb = smem_u32(sm);
    const int tid = threadIdx.x;
    const int warp = tid >> 5, lane = tid & 31;

    /* ---------------- aux CTAs: k_w + fcwA16 split ---------------- */
    if (blockIdx.x >= 32) {
        int aux = (int)blockIdx.x - 32;
        if (aux < 64) {
            /* attention weights for user u = aux (warp-per-row) */
            const int u = aux;
            for (int i = warp; i < S_; i += 8) {
                float ti = tt[i * U_ + u];
                float si0 = ss[((size_t)i * U_ + u) * 2 + 0];
                float si1 = ss[((size_t)i * U_ + u) * 2 + 1];
                float part = 0.0f;
                for (int j = lane; j < S_; j += 32) {
                    float wv = 0.0f;
                    if (j <= i) {
                        float dt = ti - tt[j * U_ + u];
                        float d0 = si0 - ss[((size_t)j * U_ + u) * 2 + 0];
                        float d1 = si1 - ss[((size_t)j * U_ + u) * 2 + 1];
                        float ds = sqrtf(d0 * d0 + d1 * d1);
                        float ft = (cosf(dt * (2.0f * PI_F / 86400.0f)) + 1.0f) * 0.5f
                                 * expf(-(dt / 86400.0f) * 0.1f);
                        float fs = expf(-ds * 100.0f);
                        wv = ft * fs + 1e-10f;
                    }
                    w16o[((size_t)u * S_ + i) * S_ + j] = __float2half(wv);
                    part += wv;
                }
#pragma unroll
                for (int o = 16; o > 0; o >>= 1)
                    part += __shfl_xor_sync(0xffffffffu, part, o);
                if (lane == 0) deno[u * S_ + i] = part;
            }
        } else {
            /* fcwA16 split: grid-stride over vec8 (pitch 1280, col0 0) */
            const int a = aux - 64;              /* 0..35 */
            const size_t total8 = ((size_t)VPAD << 9) >> 3;
            for (size_t gidx = (size_t)a * 256 + tid; gidx < total8;
                 gidx += (size_t)36 * 256) {
                size_t idx = gidx << 3;
                int r = (int)(idx >> 9);
                int c = (int)idx & 511;
                float4 v0, v1;
                if (r < V_) {
                    const float* p = fcw + (size_t)r * 1280 + c;
                    v0 = *(const float4*)p;
                    v1 = *(const float4*)(p + 4);
                } else {
                    v0 = make_float4(0.f, 0.f, 0.f, 0.f);
                    v1 = v0;
                }
                float vv[8] = { v0.x, v0.y, v0.z, v0.w, v1.x, v1.y, v1.z, v1.w };
                uint32_t hp[4];
#pragma unroll
                for (int i = 0; i < 4; i++) {
                    __half aa = __float2half(vv[2 * i]);
                    __half bb = __float2half(vv[2 * i + 1]);
                    hp[i] = (uint32_t)__half_as_ushort(aa)
                          | ((uint32_t)__half_as_ushort(bb) << 16);
                }
                *(uint4*)(fcwA + idx) = make_uint4(hp[0], hp[1], hp[2], hp[3]);
            }
        }
        return;
    }

    /* ---------------------- RNN CTAs (0..31) ---------------------- */
    const int ug = (int)blockIdx.x >> 2;
    uint32_t rank;
    asm("mov.u32 %0, %%cluster_ctarank;" : "=r"(rank));
    const int row0 = (int)rank * 128;

    __half* wst = (__half*)(sm + R3_WST);
    for (int idx = tid; idx < 128 * 64; idx += 256) {
        int r = idx >> 6, c8 = (idx & 63) << 3;
        uint4 v = *(const uint4*)&Whh16[(size_t)(row0 + r) * H_ + c8];
        *(uint4*)&wst[r * RWPAD + c8] = v;
    }
    __syncthreads();

    uint32_t A[32][4];
    {
        const uint32_t la = (uint32_t)(lane & 15) * (RWPAD * 2)
                          + (uint32_t)(lane >> 4) * 16u;
        const uint32_t wbase = sb + R3_WST + (uint32_t)warp * 16u * (RWPAD * 2);
#pragma unroll
        for (int kt = 0; kt < 32; kt++)
            LDSM4(A[kt][0], A[kt][1], A[kt][2], A[kt][3],
                  wbase + la + (uint32_t)kt * 32u);
    }

    __half* hb0p = (__half*)(sm + R3_HB0);
    for (int idx = tid; idx < 512 * 8; idx += 256) {
        int k = idx >> 3, u = idx & 7;
        hb0p[k * 8 + u] = __float2half(h0[(size_t)(ug * 8 + u) * H_ + k]);
    }
    __syncthreads();
    CLUSTER_SYNC();

    const int g = lane >> 2, tig = lane & 3;
    const int kr0 = row0 + warp * 16 + g;
    const int u0 = ug * 8 + tig * 2;
    const uint32_t lb16 = (uint32_t)(lane & 15) * 16u;

    float pv[4];
    {
        int xa = __ldg(x + u0), xb = __ldg(x + u0 + 1);
        int ta = __ldg(ts + u0), tb = __ldg(ts + u0 + 1);
        pv[0] = __ldg(E2 + (size_t)xa * H_ + kr0)     + __ldg(T2 + (size_t)ta * H_ + kr0);
        pv[1] = __ldg(E2 + (size_t)xb * H_ + kr0)     + __ldg(T2 + (size_t)tb * H_ + kr0);
        pv[2] = __ldg(E2 + (size_t)xa * H_ + kr0 + 8) + __ldg(T2 + (size_t)ta * H_ + kr0 + 8);
        pv[3] = __ldg(E2 + (size_t)xb * H_ + kr0 + 8) + __ldg(T2 + (size_t)tb * H_ + kr0 + 8);
    }

    for (int s = 0; s < steps; s++) {
        const uint32_t hb = sb + ((s & 1) ? R3_HB1 : R3_HB0);

        float a0[4] = {0.f,0.f,0.f,0.f}, a1[4] = {0.f,0.f,0.f,0.f};
        float a2[4] = {0.f,0.f,0.f,0.f}, a3[4] = {0.f,0.f,0.f,0.f};
#pragma unroll
        for (int kt = 0; kt < 32; kt += 4) {
            uint32_t b0[2], b1[2], b2[2], b3[2];
            LDSM2T(b0[0], b0[1], hb + (uint32_t)((kt + 0) * 16) * 16u + lb16);
            LDSM2T(b1[0], b1[1], hb + (uint32_t)((kt + 1) * 16) * 16u + lb16);
            LDSM2T(b2[0], b2[1], hb + (uint32_t)((kt + 2) * 16) * 16u + lb16);
            LDSM2T(b3[0], b3[1], hb + (uint32_t)((kt + 3) * 16) * 16u + lb16);
            mma16816h(a0, A[kt + 0], b0);
            mma16816h(a1, A[kt + 1], b1);
            mma16816h(a2, A[kt + 2], b2);
            mma16816h(a3, A[kt + 3], b3);
        }
        float acc[4];
#pragma unroll
        for (int q = 0; q < 4; q++) acc[q] = (a0[q] + a1[q]) + (a2[q] + a3[q]);

        float hv0 = tanh_fast(pv[0] + acc[0]);
        float hv1 = tanh_fast(pv[1] + acc[1]);
        float hv2 = tanh_fast(pv[2] + acc[2]);
        float hv3 = tanh_fast(pv[3] + acc[3]);

        const size_t ob = (size_t)s * U_ * H_;
        if (s == steps - 1) {
            out16[ob + (size_t)u0 * H_ + kr0]           = __float2half(hv0);
            out16[ob + (size_t)(u0 + 1) * H_ + kr0]     = __float2half(hv1);
            out16[ob + (size_t)u0 * H_ + kr0 + 8]       = __float2half(hv2);
            out16[ob + (size_t)(u0 + 1) * H_ + kr0 + 8] = __float2half(hv3);
            hfin[(size_t)u0 * H_ + kr0]           = hv0;
            hfin[(size_t)(u0 + 1) * H_ + kr0]     = hv1;
            hfin[(size_t)u0 * H_ + kr0 + 8]       = hv2;
            hfin[(size_t)(u0 + 1) * H_ + kr0 + 8] = hv3;
        } else {
            uint32_t p0 = (uint32_t)__half_as_ushort(__float2half(hv0))
                        | ((uint32_t)__half_as_ushort(__float2half(hv1)) << 16);
            uint32_t p1 = (uint32_t)__half_as_ushort(__float2half(hv2))
                        | ((uint32_t)__half_as_ushort(__float2half(hv3)) << 16);
            const uint32_t nbo = ((s & 1) ? R3_HB0 : R3_HB1);
            uint32_t d0 = sb + nbo + (uint32_t)(kr0 * 8 + tig * 2) * 2u;
            uint32_t d1 = sb + nbo + (uint32_t)((kr0 + 8) * 8 + tig * 2) * 2u;
#pragma unroll
            for (int r = 0; r < 4; r++) {
                if ((uint32_t)r == rank) { STS32(d0, p0); STS32(d1, p1); }
                else {
                    st_cluster_b32(d0, (uint32_t)r, p0);
                    st_cluster_b32(d1, (uint32_t)r, p1);
                }
            }
            CLUSTER_ARRIVE();
            out16[ob + (size_t)u0 * H_ + kr0]           = __float2half(hv0);
            out16[ob + (size_t)(u0 + 1) * H_ + kr0]     = __float2half(hv1);
            out16[ob + (size_t)u0 * H_ + kr0 + 8]       = __float2half(hv2);
            out16[ob + (size_t)(u0 + 1) * H_ + kr0 + 8] = __float2half(hv3);
            const int s1o = (s + 1) * U_;
            int xa = __ldg(x + s1o + u0), xb = __ldg(x + s1o + u0 + 1);
            int ta = __ldg(ts + s1o + u0), tb = __ldg(ts + s1o + u0 + 1);
            float n0 = __ldg(E2 + (size_t)xa * H_ + kr0)     + __ldg(T2 + (size_t)ta * H_ + kr0);
            float n1 = __ldg(E2 + (size_t)xb * H_ + kr0)     + __ldg(T2 + (size_t)tb * H_ + kr0);
            float n2 = __ldg(E2 + (size_t)xa * H_ + kr0 + 8) + __ldg(T2 + (size_t)ta * H_ + kr0 + 8);
            float n3 = __ldg(E2 + (size_t)xb * H_ + kr0 + 8) + __ldg(T2 + (size_t)tb * H_ + kr0 + 8);
            CLUSTER_WAIT();
            pv[0] = n0; pv[1] = n1; pv[2] = n2; pv[3] = n3;
        }
    }
}

/* ------------------------------------------------------------------ */
extern "C" void kernel_launch(void* const* d_in, const int* in_sizes, int n_in,
                              void* d_out, int out_size)
{
    const int*   x        = (const int*)  d_in[0];
    const float* t        = (const float*)d_in[1];
    const int*   t_slot   = (const int*)  d_in[2];
    const float* s        = (const float*)d_in[3];
    const int*   y_t_slot = (const int*)  d_in[5];
    const float* h0       = (const float*)d_in[7];
    const int*   act_user = (const int*)  d_in[8];
    const int*   wm       = (const int*)  d_in[9];
    const float* wwi      = (const float*)d_in[10];
    const float* sigma    = (const float*)d_in[11];
    const float* enc_w    = (const float*)d_in[12];
    const float* user_w   = (const float*)d_in[13];
    const float* wenc     = (const float*)d_in[14];
    const float* fcpt_w   = (const float*)d_in[15];
    const float* fcpt_b   = (const float*)d_in[16];
    const float* W_ih     = (const float*)d_in[17];
    const float* W_hh     = (const float*)d_in[18];
    const float* b_ih     = (const float*)d_in[19];
    const float* b_hh     = (const float*)d_in[20];
    const float* fc_w     = (const float*)d_in[21];
    const float* fc_b     = (const float*)d_in[22];
    float* out = (float*)d_out;

    void *pT, *pEnch, *pEncl, *pG1h, *pG1l, *pE2, *pTh, *pTl, *pG2h, *pG2l, *pT2;
    void *pUwh, *pUwl, *pP2, *pP3, *pCvec;
    void *pB1h, *pB1l, *pB2h, *pB2l, *pWihh, *pWihl, *pWhh16;
    void *pFcwA16, *pFcwBh, *pFcwBl, *pFcwCh, *pFcwCl;
    void *pOut16, *pHfin, *pW16, *pDen, *pOw16;
    cudaGetSymbolAddress(&pT, g_T);
    cudaGetSymbolAddress(&pEnch, g_ench);  cudaGetSymbolAddress(&pEncl, g_encl);
    cudaGetSymbolAddress(&pG1h, g_G1h);    cudaGetSymbolAddress(&pG1l, g_G1l);
    cudaGetSymbolAddress(&pE2, g_E2);
    cudaGetSymbolAddress(&pTh, g_Th);      cudaGetSymbolAddress(&pTl, g_Tl);
    cudaGetSymbolAddress(&pG2h, g_G2h);    cudaGetSymbolAddress(&pG2l, g_G2l);
    cudaGetSymbolAddress(&pT2, g_T2);
    cudaGetSymbolAddress(&pUwh, g_uwh);    cudaGetSymbolAddress(&pUwl, g_uwl);
    cudaGetSymbolAddress(&pP2, g_P2);      cudaGetSymbolAddress(&pP3, g_P3);
    cudaGetSymbolAddress(&pCvec, g_cvec);
    cudaGetSymbolAddress(&pB1h, g_B1h);    cudaGetSymbolAddress(&pB1l, g_B1l);
    cudaGetSymbolAddress(&pB2h, g_B2h);    cudaGetSymbolAddress(&pB2l, g_B2l);
    cudaGetSymbolAddress(&pWihh, g_wihh);  cudaGetSymbolAddress(&pWihl, g_wihl);
    cudaGetSymbolAddress(&pWhh16, g_whh16);
    cudaGetSymbolAddress(&pFcwA16, g_fcwA16);
    cudaGetSymbolAddress(&pFcwBh, g_fcwBh); cudaGetSymbolAddress(&pFcwBl, g_fcwBl);
    cudaGetSymbolAddress(&pFcwCh, g_fcwCh); cudaGetSymbolAddress(&pFcwCl, g_fcwCl);
    cudaGetSymbolAddress(&pOut16, g_out16); cudaGetSymbolAddress(&pHfin, g_hfin);
    cudaGetSymbolAddress(&pW16, g_w16);    cudaGetSymbolAddress(&pDen, g_den);
    cudaGetSymbolAddress(&pOw16, g_ow16);

    cudaFuncSetAttribute(hmma_gemm_b, cudaFuncAttributeMaxDynamicSharedMemorySize, GEMM_SMEM);
    cudaFuncSetAttribute(hmma_gemm16, cudaFuncAttributeMaxDynamicSharedMemorySize, GEMM16_SMEM);
    cudaFuncSetAttribute(k_att_mma,   cudaFuncAttributeMaxDynamicSharedMemorySize, ATT_SMEM);
    cudaFuncSetAttribute(k_rnn3,      cudaFuncAttributeMaxDynamicSharedMemorySize, RNN3_SMEM);

    /* h_final destination (direct write from RNN) */
    size_t yelems = (size_t)S_ * U_ * V_;
    float* hdst = ((size_t)out_size >= yelems + U_ * H_) ? (out + yelems)
                                                         : (float*)pHfin;

    /* prep + splits */
    k_week<<<168, 256>>>(sigma, wwi, wm, wenc);
    k_userw<<<128, 512>>>(user_w, act_user);
    k_cvec<<<2, 256>>>(fcpt_b, W_ih, b_ih, b_hh);
    k_split8h<<<64, 256>>>(W_hh, H_, 0, 9, 512, 512, (__half*)pWhh16);
    k_split8<<<512, 256>>>(enc_w,  H_,  0,    9, V_,  VPAD,
                           (__nv_bfloat16*)pEnch, (__nv_bfloat16*)pEncl);
    k_split8<<<64, 256>>>(W_ih,   H_,  0,    9, 512, 512,
                           (__nv_bfloat16*)pWihh, (__nv_bfloat16*)pWihl);
    k_split8<<<32, 256>>>((const float*)pT, H2_, 0, 8, 168, 256,
                           (__nv_bfloat16*)pTh, (__nv_bfloat16*)pTl);
    k_split_t<<<128, 256>>>(fcpt_w, 768, 0,   512,
                            (__nv_bfloat16*)pB1h, (__nv_bfloat16*)pB1l);
    k_split_t<<<64, 256>>>(fcpt_w, 768, 512, 256,
                            (__nv_bfloat16*)pB2h, (__nv_bfloat16*)pB2l);
    k_split8<<<512, 256>>>(fc_w,   1280, 512, 9, V_,  VPAD,
                           (__nv_bfloat16*)pFcwBh, (__nv_bfloat16*)pFcwBl);
    k_split8<<<256, 256>>>(fc_w,   1280, 1024, 8, V_, VPAD,
                           (__nv_bfloat16*)pFcwCh, (__nv_bfloat16*)pFcwCl);

    /* batched small GEMMs: {G1, G2} */
    {
        GemmTask tg1 = { (const __nv_bfloat16*)pWihh, (const __nv_bfloat16*)pWihl,
                         (const __nv_bfloat16*)pB1h,  (const __nv_bfloat16*)pB1l,
                         nullptr, nullptr,
                         (__nv_bfloat16*)pG1h, (__nv_bfloat16*)pG1l, H_, 512, 2 };
        GemmTask tg2 = { (const __nv_bfloat16*)pWihh, (const __nv_bfloat16*)pWihl,
                         (const __nv_bfloat16*)pB2h,  (const __nv_bfloat16*)pB2l,
                         nullptr, nullptr,
                         (__nv_bfloat16*)pG2h, (__nv_bfloat16*)pG2l, H_, 256, 1 };
        hmma_gemm_b<<<12, 256, GEMM_SMEM>>>(tg1, tg2, tg1, tg1, 8, 4, 0, 0);
    }
    /* batched: {E2, T2, P2, P3} */
    {
        GemmTask te2 = { (const __nv_bfloat16*)pEnch, (const __nv_bfloat16*)pEncl,
                         (const __nv_bfloat16*)pG1h,  (const __nv_bfloat16*)pG1l,
                         nullptr, (float*)pE2, nullptr, nullptr, H_, 512, 2 };
        GemmTask tt2 = { (const __nv_bfloat16*)pTh,   (const __nv_bfloat16*)pTl,
                         (const __nv_bfloat16*)pG2h,  (const __nv_bfloat16*)pG2l,
                         (const float*)pCvec, (float*)pT2, nullptr, nullptr, H2_, 512, 2 };
        GemmTask tp2 = { (const __nv_bfloat16*)pUwh,  (const __nv_bfloat16*)pUwl,
                         (const __nv_bfloat16*)pFcwBh, (const __nv_bfloat16*)pFcwBl,
                         nullptr, (float*)pP2, nullptr, nullptr, H_, V_, 20 };
        GemmTask tp3 = { (const __nv_bfloat16*)pTh,   (const __nv_bfloat16*)pTl,
                         (const __nv_bfloat16*)pFcwCh, (const __nv_bfloat16*)pFcwCl,
                         nullptr, (float*)pP3, nullptr, nullptr, H2_, V_, 20 };
        hmma_gemm_b<<<144, 256, GEMM_SMEM>>>(te2, tt2, tp2, tp3, 80, 4, 20, 40);
    }

    /* RNN (clusters 0-7) + aux k_w / fcwA16 split (CTAs 32-131) */
    k_rnn3<<<132, 256, RNN3_SMEM>>>((const float*)pE2, (const float*)pT2,
                                    x, t_slot, (const __half*)pWhh16, h0,
                                    (__half*)pOut16, hdst,
                                    t, s, fc_w,
                                    (__half*)pW16, (float*)pDen,
                                    (__half*)pFcwA16, S_);

    /* attention */
    k_att_mma<<<dim3(2, 2, U_), 256, ATT_SMEM>>>(
        (const __half*)pW16, (const __half*)pOut16,
        (const float*)pDen, (__half*)pOw16);

    /* final projection */
    hmma_gemm16<<<dim3(VPAD / 256, MSU / 128), 256, GEMM16_SMEM>>>(
        (const __half*)pOw16, (const __half*)pFcwA16,
        fc_b, (const float*)pP2, (const float*)pP3, y_t_slot,
        out, H_, V_);
}

// round 17
// speedup vs baseline: 1.2206x; 1.0085x over previous
#include <cuda_runtime.h>
#include <cuda_bf16.h>
#include <cuda_fp16.h>
#include <math.h>
#include <stdint.h>

#define S_  256
#define U_  64
#define H_  512
#define H2_ 256
#define V_  5000
#define MSU 16384
#define VPAD 5120
#define PI_F 3.14159265358979323846f

/* ------------------------- device scratch ------------------------- */
__device__ __nv_bfloat16 g_ench [(size_t)VPAD * H_];
__device__ __nv_bfloat16 g_encl [(size_t)VPAD * H_];
__device__ __nv_bfloat16 g_G1h  [512 * H_];
__device__ __nv_bfloat16 g_G1l  [512 * H_];
__device__ float         g_E2   [(size_t)VPAD * H_];
__device__ __nv_bfloat16 g_Th   [256 * H2_];
__device__ __nv_bfloat16 g_Tl   [256 * H2_];
__device__ __nv_bfloat16 g_G2h  [512 * H2_];
__device__ __nv_bfloat16 g_G2l  [512 * H2_];
__device__ float         g_T2   [256 * H_];
__device__ __nv_bfloat16 g_uwh  [128 * H_];
__device__ __nv_bfloat16 g_uwl  [128 * H_];
__device__ float         g_P2   [(size_t)128 * V_];
__device__ float         g_P3   [(size_t)256 * V_];
__device__ __nv_bfloat16 g_B1h  [512 * H_];
__device__ __nv_bfloat16 g_B1l  [512 * H_];
__device__ __nv_bfloat16 g_B2h  [256 * H_];
__device__ __nv_bfloat16 g_B2l  [256 * H_];
__device__ __nv_bfloat16 g_wihh [512 * H_];
__device__ __nv_bfloat16 g_wihl [512 * H_];
__device__ __half        g_whh16[512 * H_];
__device__ __half        g_fcwA16[(size_t)VPAD * H_];
__device__ __nv_bfloat16 g_fcwBh[(size_t)VPAD * H_];
__device__ __nv_bfloat16 g_fcwBl[(size_t)VPAD * H_];
__device__ __nv_bfloat16 g_fcwCh[(size_t)VPAD * H2_];
__device__ __nv_bfloat16 g_fcwCl[(size_t)VPAD * H2_];
__device__ float         g_cvec [H_];
__device__ __half        g_out16[(size_t)MSU * H_];
__device__ float         g_hfin [U_ * H_];
__device__ __half        g_w16  [(size_t)U_ * S_ * S_];
__device__ float         g_den  [(size_t)U_ * S_];
__device__ __half        g_ow16 [(size_t)MSU * H_];

/* ---------------------------- helpers ----------------------------- */
__device__ __forceinline__ uint32_t smem_u32(const void* p) {
    uint32_t a;
    asm("{ .reg .u64 t; cvta.to.shared.u64 t, %1; cvt.u32.u64 %0, t; }"
        : "=r"(a) : "l"(p));
    return a;
}
#define CP_ASYNC16(dst, src) \
    asm volatile("cp.async.cg.shared.global [%0], [%1], 16;" :: "r"(dst), "l"(src))
#define CP_COMMIT() asm volatile("cp.async.commit_group;" ::: "memory")
#define CP_WAIT(n)  asm volatile("cp.async.wait_group %0;" :: "n"(n) : "memory")
#define STS32(addr, v) \
    asm volatile("st.shared.b32 [%0], %1;" :: "r"(addr), "r"(v) : "memory")
#define LDSM4(r0, r1, r2, r3, a) \
    asm volatile("ldmatrix.sync.aligned.m8n8.x4.shared.b16 {%0,%1,%2,%3}, [%4];" \
        : "=r"(r0), "=r"(r1), "=r"(r2), "=r"(r3) : "r"(a))
#define LDSM2T(r0, r1, a) \
    asm volatile("ldmatrix.sync.aligned.m8n8.x2.trans.shared.b16 {%0,%1}, [%2];" \
        : "=r"(r0), "=r"(r1) : "r"(a))
#define LDSM4T(r0, r1, r2, r3, a) \
    asm volatile("ldmatrix.sync.aligned.m8n8.x4.trans.shared.b16 {%0,%1,%2,%3}, [%4];" \
        : "=r"(r0), "=r"(r1), "=r"(r2), "=r"(r3) : "r"(a))
#define CLUSTER_ARRIVE() \
    asm volatile("barrier.cluster.arrive.aligned;" ::: "memory")
#define CLUSTER_WAIT() \
    asm volatile("barrier.cluster.wait.aligned;" ::: "memory")
#define CLUSTER_SYNC() do { CLUSTER_ARRIVE(); CLUSTER_WAIT(); } while (0)

__device__ __forceinline__ void st_cluster_b32(uint32_t addr, uint32_t rank, uint32_t v) {
    asm volatile(
        "{ .reg .b32 ra; mapa.shared::cluster.u32 ra, %0, %1; "
        "st.shared::cluster.b32 [ra], %2; }"
        :: "r"(addr), "r"(rank), "r"(v) : "memory");
}
__device__ __forceinline__ float tanh_fast(float v) {
    float r; asm("tanh.approx.f32 %0, %1;" : "=f"(r) : "f"(v)); return r;
}
__device__ __forceinline__ void mma16816(float* c, const uint32_t* a, const uint32_t* b)
{
    asm volatile(
        "mma.sync.aligned.m16n8k16.row.col.f32.bf16.bf16.f32 "
        "{%0,%1,%2,%3}, {%4,%5,%6,%7}, {%8,%9}, {%0,%1,%2,%3};"
        : "+f"(c[0]), "+f"(c[1]), "+f"(c[2]), "+f"(c[3])
        : "r"(a[0]), "r"(a[1]), "r"(a[2]), "r"(a[3]), "r"(b[0]), "r"(b[1]));
}
__device__ __forceinline__ void mma16816h(float* c, const uint32_t* a, const uint32_t* b)
{
    asm volatile(
        "mma.sync.aligned.m16n8k16.row.col.f32.f16.f16.f32 "
        "{%0,%1,%2,%3}, {%4,%5,%6,%7}, {%8,%9}, {%0,%1,%2,%3};"
        : "+f"(c[0]), "+f"(c[1]), "+f"(c[2]), "+f"(c[3])
        : "r"(a[0]), "r"(a[1]), "r"(a[2]), "r"(a[3]), "r"(b[0]), "r"(b[1]));
}
__device__ __forceinline__ void split2(float v, __nv_bfloat16& h, __nv_bfloat16& l)
{
    h = __float2bfloat16(v);
    l = __float2bfloat16(v - __bfloat162float(h));
}

/* -------------- batched split-bf16 HMMA GEMM (3-term) -------------- */
struct GemmTask {
    const __nv_bfloat16 *Ah, *Al, *Bh, *Bl;
    const float* bias1;
    float* Cf;
    __nv_bfloat16 *Ch, *Cl;
    int K, Nreal, nx;
};

#define SWH 40
#define STAGE_B  61440
#define OFF_AL   10240
#define OFF_BH   20480
#define OFF_BL   40960
#define GEMM_SMEM (2 * STAGE_B)

__global__ __launch_bounds__(256, 1)
void hmma_gemm_b(GemmTask t0, GemmTask t1, GemmTask t2, GemmTask t3,
                 int c0, int c1, int c2, int c3)
{
    extern __shared__ char smem[];
    const uint32_t sbase = smem_u32(smem);
    const int tid  = threadIdx.x;

    GemmTask t;
    int lin = blockIdx.x;
    if (lin < c0)                    { t = t0; }
    else if ((lin -= c0) < c1)       { t = t1; }
    else if ((lin -= c1) < c2)       { t = t2; }
    else                             { lin -= c2; t = t3; }
    const int m0 = (lin / t.nx) * 128;
    const int n0 = (lin % t.nx) * 256;
    const __nv_bfloat16* __restrict__ Ah = t.Ah;
    const __nv_bfloat16* __restrict__ Al = t.Al;
    const __nv_bfloat16* __restrict__ Bh = t.Bh;
    const __nv_bfloat16* __restrict__ Bl = t.Bl;
    const int K = t.K, Nreal = t.Nreal;

    const int warp = tid >> 5, lane = tid & 31;
    const int wm = warp >> 2, wn = warp & 3;
    const int g  = lane >> 2, tig = lane & 3;
    const int L = K >> 5;

    const uint32_t aoffc = ((uint32_t)(wm * 64 + (lane & 15)) * SWH) * 2u
                         + (uint32_t)(lane >> 4) * 16u;
    const int sel  = (lane >> 3) & 3;
    const uint32_t boffc = ((uint32_t)(wn * 64 + ((sel & 2) << 2) + (lane & 7)) * SWH) * 2u
                         + (uint32_t)(sel & 1) * 16u;

    float acc[4][8][4];
#pragma unroll
    for (int mi = 0; mi < 4; mi++)
#pragma unroll
        for (int ni = 0; ni < 8; ni++)
#pragma unroll
            for (int q = 0; q < 4; q++) acc[mi][ni][q] = 0.0f;

    auto load_stage = [&](int chunk, int buf) {
        const uint32_t sg = sbase + (uint32_t)buf * STAGE_B;
        const int k0 = chunk << 5;
#pragma unroll 2
        for (int idx = tid; idx < 512; idx += 256) {
            int r = idx >> 2, c = idx & 3;
            uint32_t dsto = (uint32_t)(r * SWH + c * 8) * 2u;
            size_t srco = (size_t)(m0 + r) * K + k0 + c * 8;
            CP_ASYNC16(sg + dsto,            Ah + srco);
            CP_ASYNC16(sg + OFF_AL + dsto,   Al + srco);
        }
#pragma unroll 4
        for (int idx = tid; idx < 1024; idx += 256) {
            int r = idx >> 2, c = idx & 3;
            uint32_t dsto = (uint32_t)(r * SWH + c * 8) * 2u;
            size_t srco = (size_t)(n0 + r) * K + k0 + c * 8;
            CP_ASYNC16(sg + OFF_BH + dsto,   Bh + srco);
            CP_ASYNC16(sg + OFF_BL + dsto,   Bl + srco);
        }
        CP_COMMIT();
    };

    load_stage(0, 0);

    for (int i = 0; i < L; i++) {
        if (i + 1 < L) { load_stage(i + 1, (i + 1) & 1); CP_WAIT(1); }
        else           { CP_WAIT(0); }
        __syncthreads();

        const uint32_t sg = sbase + (uint32_t)(i & 1) * STAGE_B;
#pragma unroll
        for (int ks = 0; ks < 2; ks++) {
            const uint32_t kb = (uint32_t)ks * 32u;
            uint32_t ah[4][4], al[4][4], bb[8][2];
#pragma unroll
            for (int mi = 0; mi < 4; mi++)
                LDSM4(ah[mi][0], ah[mi][1], ah[mi][2], ah[mi][3],
                      sg + kb + aoffc + (uint32_t)mi * (16 * SWH * 2));
#pragma unroll
            for (int n2 = 0; n2 < 4; n2++)
                LDSM4(bb[2*n2][0], bb[2*n2][1], bb[2*n2+1][0], bb[2*n2+1][1],
                      sg + OFF_BH + kb + boffc + (uint32_t)n2 * (16 * SWH * 2));
#pragma unroll
            for (int mi = 0; mi < 4; mi++)
#pragma unroll
                for (int ni = 0; ni < 8; ni++)
                    mma16816(acc[mi][ni], ah[mi], bb[ni]);
#pragma unroll
            for (int mi = 0; mi < 4; mi++)
                LDSM4(al[mi][0], al[mi][1], al[mi][2], al[mi][3],
                      sg + OFF_AL + kb + aoffc + (uint32_t)mi * (16 * SWH * 2));
#pragma unroll
            for (int mi = 0; mi < 4; mi++)
#pragma unroll
                for (int ni = 0; ni < 8; ni++)
                    mma16816(acc[mi][ni], al[mi], bb[ni]);
#pragma unroll
            for (int n2 = 0; n2 < 4; n2++)
                LDSM4(bb[2*n2][0], bb[2*n2][1], bb[2*n2+1][0], bb[2*n2+1][1],
                      sg + OFF_BL + kb + boffc + (uint32_t)n2 * (16 * SWH * 2));
#pragma unroll
            for (int mi = 0; mi < 4; mi++)
#pragma unroll
                for (int ni = 0; ni < 8; ni++)
                    mma16816(acc[mi][ni], ah[mi], bb[ni]);
        }
        __syncthreads();
    }

#pragma unroll
    for (int mi = 0; mi < 4; mi++) {
        const int row0 = m0 + wm * 64 + mi * 16 + g;
#pragma unroll
        for (int ni = 0; ni < 8; ni++) {
            const int n = n0 + wn * 64 + ni * 8 + tig * 2;
#pragma unroll
            for (int q = 0; q < 4; q++) {
                int rr = row0 + ((q >= 2) ? 8 : 0);
                int nn = n + (q & 1);
                if (nn >= Nreal) continue;
                float f = acc[mi][ni][q];
                if (t.bias1) f += t.bias1[nn];
                if (t.Cf) {
                    t.Cf[(size_t)rr * Nreal + nn] = f;
                } else {
                    __nv_bfloat16 hi, lo;
                    split2(f, hi, lo);
                    t.Ch[(size_t)rr * Nreal + nn] = hi;
                    t.Cl[(size_t)rr * Nreal + nn] = lo;
                }
            }
        }
    }
}

/* ----------------- fp16 HMMA GEMM (final projection) --------------- */
#define SWH2      72
#define G16_OFFB  18432
#define G16_STAGE 55296
#define GEMM16_SMEM (2 * G16_STAGE)

__global__ __launch_bounds__(256, 1)
void hmma_gemm16(const __half* __restrict__ A, const __half* __restrict__ B,
                 const float* __restrict__ bias1,
                 const float* __restrict__ add1,
                 const float* __restrict__ add2, const int* __restrict__ idx2,
                 float* __restrict__ Cf, int K, int Nreal)
{
    extern __shared__ char smem[];
    const uint32_t sbase = smem_u32(smem);
    const int tid  = threadIdx.x;
    const int m0   = blockIdx.y * 128;
    const int n0   = blockIdx.x * 256;
    const int warp = tid >> 5, lane = tid & 31;
    const int wm = warp >> 2, wn = warp & 3;
    const int g  = lane >> 2, tig = lane & 3;
    const int L = K >> 6;

    const uint32_t aoffc = ((uint32_t)(wm * 64 + (lane & 15)) * SWH2) * 2u
                         + (uint32_t)(lane >> 4) * 16u;
    const int sel  = (lane >> 3) & 3;
    const uint32_t boffc = ((uint32_t)(wn * 64 + ((sel & 2) << 2) + (lane & 7)) * SWH2) * 2u
                         + (uint32_t)(sel & 1) * 16u;

    float acc[4][8][4];
#pragma unroll
    for (int mi = 0; mi < 4; mi++)
#pragma unroll
        for (int ni = 0; ni < 8; ni++)
#pragma unroll
            for (int q = 0; q < 4; q++) acc[mi][ni][q] = 0.0f;

    auto load_stage = [&](int chunk, int buf) {
        const uint32_t sg = sbase + (uint32_t)buf * G16_STAGE;
        const int k0 = chunk << 6;
#pragma unroll 4
        for (int idx = tid; idx < 1024; idx += 256) {
            int r = idx >> 3, c = idx & 7;
            CP_ASYNC16(sg + (uint32_t)(r * SWH2 + c * 8) * 2u,
                       A + (size_t)(m0 + r) * K + k0 + c * 8);
        }
#pragma unroll 8
        for (int idx = tid; idx < 2048; idx += 256) {
            int r = idx >> 3, c = idx & 7;
            CP_ASYNC16(sg + G16_OFFB + (uint32_t)(r * SWH2 + c * 8) * 2u,
                       B + (size_t)(n0 + r) * K + k0 + c * 8);
        }
        CP_COMMIT();
    };

    load_stage(0, 0);

    for (int i = 0; i < L; i++) {
        if (i + 1 < L) { load_stage(i + 1, (i + 1) & 1); CP_WAIT(1); }
        else           { CP_WAIT(0); }
        __syncthreads();

        const uint32_t sg = sbase + (uint32_t)(i & 1) * G16_STAGE;
#pragma unroll
        for (int ks = 0; ks < 4; ks++) {
            const uint32_t kb = (uint32_t)ks * 32u;
            uint32_t ah[4][4], bb[8][2];
#pragma unroll
            for (int mi = 0; mi < 4; mi++)
                LDSM4(ah[mi][0], ah[mi][1], ah[mi][2], ah[mi][3],
                      sg + kb + aoffc + (uint32_t)mi * (16 * SWH2 * 2));
#pragma unroll
            for (int n2 = 0; n2 < 4; n2++)
                LDSM4(bb[2*n2][0], bb[2*n2][1], bb[2*n2+1][0], bb[2*n2+1][1],
                      sg + G16_OFFB + kb + boffc + (uint32_t)n2 * (16 * SWH2 * 2));
#pragma unroll
            for (int mi = 0; mi < 4; mi++)
#pragma unroll
                for (int ni = 0; ni < 8; ni++)
                    mma16816h(acc[mi][ni], ah[mi], bb[ni]);
        }
        __syncthreads();
    }

#pragma unroll
    for (int mi = 0; mi < 4; mi++) {
        const int row0 = m0 + wm * 64 + mi * 16 + g;
        int i2[2] = { 0, 0 };
        if (add2) { i2[0] = idx2[row0]; i2[1] = idx2[row0 + 8]; }
#pragma unroll
        for (int ni = 0; ni < 8; ni++) {
            const int n = n0 + wn * 64 + ni * 8 + tig * 2;
#pragma unroll
            for (int q = 0; q < 4; q++) {
                int rr = row0 + ((q >= 2) ? 8 : 0);
                int nn = n + (q & 1);
                if (nn >= Nreal) continue;
                float f = acc[mi][ni][q] + bias1[nn]
                        + add1[(size_t)(rr & 63) * Nreal + nn]
                        + add2[(size_t)i2[q >> 1] * Nreal + nn];
                Cf[(size_t)rr * Nreal + nn] = f;
            }
        }
    }
}

/* ------------------------- attention HMMA -------------------------- */
#define ATT_SWA   40
#define ATT_SWB   264
#define ATT_B_OFF (128 * ATT_SWA * 2)
#define ATT_STAGE (ATT_B_OFF + 32 * ATT_SWB * 2)
#define ATT_SMEM  (2 * ATT_STAGE)

__global__ __launch_bounds__(256, 1)
void k_att_mma(const __half* __restrict__ w16, const __half* __restrict__ o16,
               const float* __restrict__ den, __half* __restrict__ ow)
{
    extern __shared__ char smem[];
    const uint32_t sbase = smem_u32(smem);
    const int tid  = threadIdx.x;
    const int u    = blockIdx.z;
    const int i0   = blockIdx.y * 128;
    const int h0   = blockIdx.x * 256;
    const int warp = tid >> 5, lane = tid & 31;
    const int wm = warp >> 2, wn = warp & 3;
    const int g  = lane >> 2, tig = lane & 3;
    const int L  = (i0 + 128) >> 5;

    const uint32_t aoffc = ((uint32_t)(wm * 64 + (lane & 15)) * ATT_SWA) * 2u
                         + (uint32_t)(lane >> 4) * 16u;
    const uint32_t boffc = ((uint32_t)((lane & 7) + ((lane >> 3) & 1) * 8) * ATT_SWB) * 2u
                         + (uint32_t)(lane >> 4) * 16u;

    float acc[4][8][4];
#pragma unroll
    for (int mi = 0; mi < 4; mi++)
#pragma unroll
        for (int ni = 0; ni < 8; ni++)
#pragma unroll
            for (int q = 0; q < 4; q++) acc[mi][ni][q] = 0.0f;

    auto load_stage = [&](int chunk, int buf) {
        const uint32_t sg = sbase + (uint32_t)buf * ATT_STAGE;
        const int j0 = chunk << 5;
#pragma unroll 2
        for (int idx = tid; idx < 512; idx += 256) {
            int r = idx >> 2, c = idx & 3;
            CP_ASYNC16(sg + (uint32_t)(r * ATT_SWA + c * 8) * 2u,
                       w16 + (size_t)u * (S_ * S_) + (size_t)(i0 + r) * S_ + j0 + c * 8);
        }
#pragma unroll 4
        for (int idx = tid; idx < 1024; idx += 256) {
            int r = idx >> 5, c = idx & 31;
            CP_ASYNC16(sg + ATT_B_OFF + (uint32_t)(r * ATT_SWB + c * 8) * 2u,
                       o16 + ((size_t)(j0 + r) * U_ + u) * H_ + h0 + c * 8);
        }
        CP_COMMIT();
    };

    load_stage(0, 0);

    for (int i = 0; i < L; i++) {
        if (i + 1 < L) { load_stage(i + 1, (i + 1) & 1); CP_WAIT(1); }
        else           { CP_WAIT(0); }
        __syncthreads();

        const uint32_t sg = sbase + (uint32_t)(i & 1) * ATT_STAGE;
#pragma unroll
        for (int ks = 0; ks < 2; ks++) {
            uint32_t ah[4][4], bb[8][2];
#pragma unroll
            for (int mi = 0; mi < 4; mi++)
                LDSM4(ah[mi][0], ah[mi][1], ah[mi][2], ah[mi][3],
                      sg + (uint32_t)ks * 32u + aoffc + (uint32_t)mi * (16 * ATT_SWA * 2));
#pragma unroll
            for (int n2 = 0; n2 < 4; n2++)
                LDSM4T(bb[2*n2][0], bb[2*n2][1], bb[2*n2+1][0], bb[2*n2+1][1],
                       sg + ATT_B_OFF + (uint32_t)ks * (16 * ATT_SWB * 2) + boffc
                          + (uint32_t)(wn * 64 + n2 * 16) * 2u);
#pragma unroll
            for (int mi = 0; mi < 4; mi++)
#pragma unroll
                for (int ni = 0; ni < 8; ni++)
                    mma16816h(acc[mi][ni], ah[mi], bb[ni]);
        }
        __syncthreads();
    }

#pragma unroll
    for (int mi = 0; mi < 4; mi++) {
        const int ia = i0 + wm * 64 + mi * 16 + g;
        const float d0 = 1.0f / den[u * S_ + ia];
        const float d1 = 1.0f / den[u * S_ + ia + 8];
#pragma unroll
        for (int ni = 0; ni < 8; ni++) {
            const int h = h0 + wn * 64 + ni * 8 + tig * 2;
            uint32_t p0 = (uint32_t)__half_as_ushort(__float2half(acc[mi][ni][0] * d0))
                        | ((uint32_t)__half_as_ushort(__float2half(acc[mi][ni][1] * d0)) << 16);
            uint32_t p1 = (uint32_t)__half_as_ushort(__float2half(acc[mi][ni][2] * d1))
                        | ((uint32_t)__half_as_ushort(__float2half(acc[mi][ni][3] * d1)) << 16);
            ((uint32_t*)ow)[(((size_t)ia      * U_ + u) * H_ + h) >> 1] = p0;
            ((uint32_t*)ow)[(((size_t)(ia + 8)* U_ + u) * H_ + h) >> 1] = p1;
        }
    }
}

/* ------------- split helpers (device-side, shared logic) ----------- */
__device__ __forceinline__ void split8_body(
    const float* __restrict__ src, int pitch, int col0, int lcols,
    int rows, int padRows, __nv_bfloat16* dh, __nv_bfloat16* dl,
    int blk, int nblk, int tid)
{
    const int cmask = (1 << lcols) - 1;
    const size_t total8 = ((size_t)padRows << lcols) >> 3;
    for (size_t gidx = (size_t)blk * 256 + tid; gidx < total8;
         gidx += (size_t)nblk * 256) {
        size_t idx = gidx << 3;
        int r = (int)(idx >> lcols);
        int c = (int)idx & cmask;
        float4 v0, v1;
        if (r < rows) {
            const float* p = src + (size_t)r * pitch + col0 + c;
            v0 = *(const float4*)p;
            v1 = *(const float4*)(p + 4);
        } else {
            v0 = make_float4(0.f, 0.f, 0.f, 0.f);
            v1 = v0;
        }
        float vv[8] = { v0.x, v0.y, v0.z, v0.w, v1.x, v1.y, v1.z, v1.w };
        uint32_t hp[4], lp[4];
#pragma unroll
        for (int i = 0; i < 4; i++) {
            __nv_bfloat16 h0, l0, h1, l1;
            split2(vv[2 * i],     h0, l0);
            split2(vv[2 * i + 1], h1, l1);
            hp[i] = (uint32_t)*(uint16_t*)&h0 | ((uint32_t)*(uint16_t*)&h1 << 16);
            lp[i] = (uint32_t)*(uint16_t*)&l0 | ((uint32_t)*(uint16_t*)&l1 << 16);
        }
        *(uint4*)(dh + idx) = make_uint4(hp[0], hp[1], hp[2], hp[3]);
        *(uint4*)(dl + idx) = make_uint4(lp[0], lp[1], lp[2], lp[3]);
    }
}

__device__ __forceinline__ void split8h_body(
    const float* __restrict__ src, int pitch, int col0, int lcols,
    int rows, int padRows, __half* d, int blk, int nblk, int tid)
{
    const int cmask = (1 << lcols) - 1;
    const size_t total8 = ((size_t)padRows << lcols) >> 3;
    for (size_t gidx = (size_t)blk * 256 + tid; gidx < total8;
         gidx += (size_t)nblk * 256) {
        size_t idx = gidx << 3;
        int r = (int)(idx >> lcols);
        int c = (int)idx & cmask;
        float4 v0, v1;
        if (r < rows) {
            const float* p = src + (size_t)r * pitch + col0 + c;
            v0 = *(const float4*)p;
            v1 = *(const float4*)(p + 4);
        } else {
            v0 = make_float4(0.f, 0.f, 0.f, 0.f);
            v1 = v0;
        }
        float vv[8] = { v0.x, v0.y, v0.z, v0.w, v1.x, v1.y, v1.z, v1.w };
        uint32_t hp[4];
#pragma unroll
        for (int i = 0; i < 4; i++) {
            __half a = __float2half(vv[2 * i]);
            __half b = __float2half(vv[2 * i + 1]);
            hp[i] = (uint32_t)__half_as_ushort(a) | ((uint32_t)__half_as_ushort(b) << 16);
        }
        *(uint4*)(d + idx) = make_uint4(hp[0], hp[1], hp[2], hp[3]);
    }
}

__device__ __forceinline__ void split_t_body(
    const float* __restrict__ src, int pitch, int col0, int crows,
    __nv_bfloat16* dh, __nv_bfloat16* dl, int blk, int nblk, int tid)
{
    const size_t total = (size_t)crows << 9;
    for (size_t idx = (size_t)blk * 256 + tid; idx < total;
         idx += (size_t)nblk * 256) {
        int c = (int)(idx >> 9);
        int o = (int)idx & 511;
        float v = src[(size_t)o * pitch + col0 + c];
        __nv_bfloat16 hi, lo;
        split2(v, hi, lo);
        dh[idx] = hi; dl[idx] = lo;
    }
}

/* --------- k_week: time-emb table -> split bf16 Th/Tl directly ------ */
__global__ void k_week(const float* __restrict__ sigma,
                       const float* __restrict__ wwi,
                       const int*   __restrict__ wm,
                       const float* __restrict__ wenc)
{
    const int slot = blockIdx.x;          /* 0..255 */
    const int tid  = threadIdx.x;         /* 0..255 = h */

    if (slot >= 168) {                    /* pad rows: zero */
        __nv_bfloat16 z = __float2bfloat16(0.0f);
        g_Th[slot * H2_ + tid] = z;
        g_Tl[slot * H2_ + tid] = z;
        return;
    }

    __shared__ float ww[168];
    __shared__ float red[256];

    float sig    = fabsf(sigma[slot]);
    float inv2s2 = 1.0f / (2.0f * sig * sig);
    float coef   = rsqrtf(2.0f * PI_F * sig * sig);

    float v = 0.0f;
    if (tid < 168) {
        float x = wwi[slot * 168 + tid];
        v = coef * expf(-x * x * inv2s2);
        ww[tid] = v;
    }
    red[tid] = v;
    __syncthreads();
    for (int off = 128; off > 0; off >>= 1) {
        if (tid < off) red[tid] += red[tid + off];
        __syncthreads();
    }
    const float inv = 1.0f / red[0];

    float acc = 0.0f;
    for (int k = 0; k < 168; k++) {
        int row = wm[slot * 168 + k];
        acc += (ww[k] * inv) * wenc[row * H2_ + tid];
    }
    __nv_bfloat16 hi, lo;
    split2(acc, hi, lo);
    g_Th[slot * H2_ + tid] = hi;
    g_Tl[slot * H2_ + tid] = lo;
}

/* ---- k_prep1: userw + cvec + Whh16 + W_ih + B1 + B2 (450 CTAs) ---- */
__global__ __launch_bounds__(256)
void k_prep1(const float* __restrict__ user_w, const int* __restrict__ au,
             const float* __restrict__ fcpt_b, const float* __restrict__ W_ih,
             const float* __restrict__ b_ih, const float* __restrict__ b_hh,
             const float* __restrict__ W_hh, const float* __restrict__ fcpt_w)
{
    const int blk = blockIdx.x;
    const int tid = threadIdx.x;

    if (blk < 128) {                       /* userw: u = blk, c in 2 passes */
        const int u = blk;
#pragma unroll
        for (int p = 0; p < 2; p++) {
            int c = p * 256 + tid;
            float v = 0.0f;
            if (u < U_) v = user_w[(size_t)au[u] * H_ + c];
            __nv_bfloat16 hi, lo;
            split2(v, hi, lo);
            g_uwh[u * H_ + c] = hi;
            g_uwl[u * H_ + c] = lo;
        }
    } else if (blk < 130) {                /* cvec: n = (blk-128)*256 + tid */
        const int n = (blk - 128) * 256 + tid;
        float a = b_ih[n] + b_hh[n];
        for (int k = 0; k < H_; k++) a += fcpt_b[k] * W_ih[(size_t)n * H_ + k];
        g_cvec[n] = a;
    } else if (blk < 194) {                /* Whh16 split: 64 blocks */
        split8h_body(W_hh, H_, 0, 9, 512, 512, g_whh16, blk - 130, 64, tid);
    } else if (blk < 258) {                /* W_ih split: 64 blocks */
        split8_body(W_ih, H_, 0, 9, 512, 512, g_wihh, g_wihl, blk - 194, 64, tid);
    } else if (blk < 386) {                /* B1 transpose split: 128 blocks */
        split_t_body(fcpt_w, 768, 0, 512, g_B1h, g_B1l, blk - 258, 128, tid);
    } else {                               /* B2 transpose split: 64 blocks */
        split_t_body(fcpt_w, 768, 512, 256, g_B2h, g_B2l, blk - 386, 64, tid);
    }
}

/* ---------- k_prep2: enc + fcwB + fcwC splits (512 CTAs) ------------ */
__global__ __launch_bounds__(256)
void k_prep2(const float* __restrict__ enc_w, const float* __restrict__ fc_w)
{
    const int blk = blockIdx.x;
    const int tid = threadIdx.x;
    if (blk < 256) {
        split8_body(enc_w, H_, 0, 9, V_, VPAD, g_ench, g_encl, blk, 256, tid);
    } else if (blk < 416) {
        split8_body(fc_w, 1280, 512, 9, V_, VPAD, g_fcwBh, g_fcwBl, blk - 256, 160, tid);
    } else {
        split8_body(fc_w, 1280, 1024, 8, V_, VPAD, g_fcwCh, g_fcwCl, blk - 416, 96, tid);
    }
}

/* --- RNN v6: cluster(4) RNN in clusters 0-7 + aux work CTAs 32+ ----- */
#define RWPAD 520
#define R3_WST  0
#define R3_HB0  133120
#define R3_HB1  141312
#define RNN3_SMEM 149504

__global__ __cluster_dims__(4, 1, 1) __launch_bounds__(256, 1)
void k_rnn3(const float* __restrict__ E2, const float* __restrict__ T2,
            const int* __restrict__ x, const int* __restrict__ ts,
            const __half* __restrict__ Whh16, const float* __restrict__ h0,
            __half* __restrict__ out16, float* __restrict__ hfin,
            const float* __restrict__ tt, const float* __restrict__ ss,
            const float* __restrict__ fcw,
            __half* __restrict__ w16o, float* __restrict__ deno,
            __half* __restrict__ fcwA, int steps)
{
    extern __shared__ char sm[];
    const uint32_t sb = smem_u32(sm);
    const int tid = threadIdx.x;
    const int warp = tid >> 5, lane = tid & 31;

    /* ---------------- aux CTAs: k_w + fcwA16 split ---------------- */
    if (blockIdx.x >= 32) {
        int aux = (int)blockIdx.x - 32;
        if (aux < 64) {
            const int u = aux;
            for (int i = warp; i < S_; i += 8) {
                float ti = tt[i * U_ + u];
                float si0 = ss[((size_t)i * U_ + u) * 2 + 0];
                float si1 = ss[((size_t)i * U_ + u) * 2 + 1];
                float part = 0.0f;
                for (int j = lane; j < S_; j += 32) {
                    float wv = 0.0f;
                    if (j <= i) {
                        float dt = ti - tt[j * U_ + u];
                        float d0 = si0 - ss[((size_t)j * U_ + u) * 2 + 0];
                        float d1 = si1 - ss[((size_t)j * U_ + u) * 2 + 1];
                        float ds = sqrtf(d0 * d0 + d1 * d1);
                        float ft = (cosf(dt * (2.0f * PI_F / 86400.0f)) + 1.0f) * 0.5f
                                 * expf(-(dt / 86400.0f) * 0.1f);
                        float fs = expf(-ds * 100.0f);
                        wv = ft * fs + 1e-10f;
                    }
                    w16o[((size_t)u * S_ + i) * S_ + j] = __float2half(wv);
                    part += wv;
                }
#pragma unroll
                for (int o = 16; o > 0; o >>= 1)
                    part += __shfl_xor_sync(0xffffffffu, part, o);
                if (lane == 0) deno[u * S_ + i] = part;
            }
        } else {
            const int a = aux - 64;
            const size_t total8 = ((size_t)VPAD << 9) >> 3;
            for (size_t gidx = (size_t)a * 256 + tid; gidx < total8;
                 gidx += (size_t)36 * 256) {
                size_t idx = gidx << 3;
                int r = (int)(idx >> 9);
                int c = (int)idx & 511;
                float4 v0, v1;
                if (r < V_) {
                    const float* p = fcw + (size_t)r * 1280 + c;
                    v0 = *(const float4*)p;
                    v1 = *(const float4*)(p + 4);
                } else {
                    v0 = make_float4(0.f, 0.f, 0.f, 0.f);
                    v1 = v0;
                }
                float vv[8] = { v0.x, v0.y, v0.z, v0.w, v1.x, v1.y, v1.z, v1.w };
                uint32_t hp[4];
#pragma unroll
                for (int i = 0; i < 4; i++) {
                    __half aa = __float2half(vv[2 * i]);
                    __half bb = __float2half(vv[2 * i + 1]);
                    hp[i] = (uint32_t)__half_as_ushort(aa)
                          | ((uint32_t)__half_as_ushort(bb) << 16);
                }
                *(uint4*)(fcwA + idx) = make_uint4(hp[0], hp[1], hp[2], hp[3]);
            }
        }
        return;
    }

    /* ---------------------- RNN CTAs (0..31) ---------------------- */
    const int ug = (int)blockIdx.x >> 2;
    uint32_t rank;
    asm("mov.u32 %0, %%cluster_ctarank;" : "=r"(rank));
    const int row0 = (int)rank * 128;

    __half* wst = (__half*)(sm + R3_WST);
    for (int idx = tid; idx < 128 * 64; idx += 256) {
        int r = idx >> 6, c8 = (idx & 63) << 3;
        uint4 v = *(const uint4*)&Whh16[(size_t)(row0 + r) * H_ + c8];
        *(uint4*)&wst[r * RWPAD + c8] = v;
    }
    __syncthreads();

    uint32_t A[32][4];
    {
        const uint32_t la = (uint32_t)(lane & 15) * (RWPAD * 2)
                          + (uint32_t)(lane >> 4) * 16u;
        const uint32_t wbase = sb + R3_WST + (uint32_t)warp * 16u * (RWPAD * 2);
#pragma unroll
        for (int kt = 0; kt < 32; kt++)
            LDSM4(A[kt][0], A[kt][1], A[kt][2], A[kt][3],
                  wbase + la + (uint32_t)kt * 32u);
    }

    __half* hb0p = (__half*)(sm + R3_HB0);
    for (int idx = tid; idx < 512 * 8; idx += 256) {
        int k = idx >> 3, u = idx & 7;
        hb0p[k * 8 + u] = __float2half(h0[(size_t)(ug * 8 + u) * H_ + k]);
    }
    __syncthreads();
    CLUSTER_SYNC();

    const int g = lane >> 2, tig = lane & 3;
    const int kr0 = row0 + warp * 16 + g;
    const int u0 = ug * 8 + tig * 2;
    const uint32_t lb16 = (uint32_t)(lane & 15) * 16u;

    float pv[4];
    {
        int xa = __ldg(x + u0), xb = __ldg(x + u0 + 1);
        int ta = __ldg(ts + u0), tb = __ldg(ts + u0 + 1);
        pv[0] = __ldg(E2 + (size_t)xa * H_ + kr0)     + __ldg(T2 + (size_t)ta * H_ + kr0);
        pv[1] = __ldg(E2 + (size_t)xb * H_ + kr0)     + __ldg(T2 + (size_t)tb * H_ + kr0);
        pv[2] = __ldg(E2 + (size_t)xa * H_ + kr0 + 8) + __ldg(T2 + (size_t)ta * H_ + kr0 + 8);
        pv[3] = __ldg(E2 + (size_t)xb * H_ + kr0 + 8) + __ldg(T2 + (size_t)tb * H_ + kr0 + 8);
    }

    for (int s = 0; s < steps; s++) {
        const uint32_t hb = sb + ((s & 1) ? R3_HB1 : R3_HB0);

        float a0[4] = {0.f,0.f,0.f,0.f}, a1[4] = {0.f,0.f,0.f,0.f};
        float a2[4] = {0.f,0.f,0.f,0.f}, a3[4] = {0.f,0.f,0.f,0.f};
#pragma unroll
        for (int kt = 0; kt < 32; kt += 4) {
            uint32_t b0[2], b1[2], b2[2], b3[2];
            LDSM2T(b0[0], b0[1], hb + (uint32_t)((kt + 0) * 16) * 16u + lb16);
            LDSM2T(b1[0], b1[1], hb + (uint32_t)((kt + 1) * 16) * 16u + lb16);
            LDSM2T(b2[0], b2[1], hb + (uint32_t)((kt + 2) * 16) * 16u + lb16);
            LDSM2T(b3[0], b3[1], hb + (uint32_t)((kt + 3) * 16) * 16u + lb16);
            mma16816h(a0, A[kt + 0], b0);
            mma16816h(a1, A[kt + 1], b1);
            mma16816h(a2, A[kt + 2], b2);
            mma16816h(a3, A[kt + 3], b3);
        }
        float acc[4];
#pragma unroll
        for (int q = 0; q < 4; q++) acc[q] = (a0[q] + a1[q]) + (a2[q] + a3[q]);

        float hv0 = tanh_fast(pv[0] + acc[0]);
        float hv1 = tanh_fast(pv[1] + acc[1]);
        float hv2 = tanh_fast(pv[2] + acc[2]);
        float hv3 = tanh_fast(pv[3] + acc[3]);

        const size_t ob = (size_t)s * U_ * H_;
        if (s == steps - 1) {
            out16[ob + (size_t)u0 * H_ + kr0]           = __float2half(hv0);
            out16[ob + (size_t)(u0 + 1) * H_ + kr0]     = __float2half(hv1);
            out16[ob + (size_t)u0 * H_ + kr0 + 8]       = __float2half(hv2);
            out16[ob + (size_t)(u0 + 1) * H_ + kr0 + 8] = __float2half(hv3);
            hfin[(size_t)u0 * H_ + kr0]           = hv0;
            hfin[(size_t)(u0 + 1) * H_ + kr0]     = hv1;
            hfin[(size_t)u0 * H_ + kr0 + 8]       = hv2;
            hfin[(size_t)(u0 + 1) * H_ + kr0 + 8] = hv3;
        } else {
            uint32_t p0 = (uint32_t)__half_as_ushort(__float2half(hv0))
                        | ((uint32_t)__half_as_ushort(__float2half(hv1)) << 16);
            uint32_t p1 = (uint32_t)__half_as_ushort(__float2half(hv2))
                        | ((uint32_t)__half_as_ushort(__float2half(hv3)) << 16);
            const uint32_t nbo = ((s & 1) ? R3_HB0 : R3_HB1);
            uint32_t d0 = sb + nbo + (uint32_t)(kr0 * 8 + tig * 2) * 2u;
            uint32_t d1 = sb + nbo + (uint32_t)((kr0 + 8) * 8 + tig * 2) * 2u;
#pragma unroll
            for (int r = 0; r < 4; r++) {
                if ((uint32_t)r == rank) { STS32(d0, p0); STS32(d1, p1); }
                else {
                    st_cluster_b32(d0, (uint32_t)r, p0);
                    st_cluster_b32(d1, (uint32_t)r, p1);
                }
            }
            CLUSTER_ARRIVE();
            out16[ob + (size_t)u0 * H_ + kr0]           = __float2half(hv0);
            out16[ob + (size_t)(u0 + 1) * H_ + kr0]     = __float2half(hv1);
            out16[ob + (size_t)u0 * H_ + kr0 + 8]       = __float2half(hv2);
            out16[ob + (size_t)(u0 + 1) * H_ + kr0 + 8] = __float2half(hv3);
            const int s1o = (s + 1) * U_;
            int xa = __ldg(x + s1o + u0), xb = __ldg(x + s1o + u0 + 1);
            int ta = __ldg(ts + s1o + u0), tb = __ldg(ts + s1o + u0 + 1);
            float n0 = __ldg(E2 + (size_t)xa * H_ + kr0)     + __ldg(T2 + (size_t)ta * H_ + kr0);
            float n1 = __ldg(E2 + (size_t)xb * H_ + kr0)     + __ldg(T2 + (size_t)tb * H_ + kr0);
            float n2 = __ldg(E2 + (size_t)xa * H_ + kr0 + 8) + __ldg(T2 + (size_t)ta * H_ + kr0 + 8);
            float n3 = __ldg(E2 + (size_t)xb * H_ + kr0 + 8) + __ldg(T2 + (size_t)tb * H_ + kr0 + 8);
            CLUSTER_WAIT();
            pv[0] = n0; pv[1] = n1; pv[2] = n2; pv[3] = n3;
        }
    }
}

/* ------------------------------------------------------------------ */
extern "C" void kernel_launch(void* const* d_in, const int* in_sizes, int n_in,
                              void* d_out, int out_size)
{
    const int*   x        = (const int*)  d_in[0];
    const float* t        = (const float*)d_in[1];
    const int*   t_slot   = (const int*)  d_in[2];
    const float* s        = (const float*)d_in[3];
    const int*   y_t_slot = (const int*)  d_in[5];
    const float* h0       = (const float*)d_in[7];
    const int*   act_user = (const int*)  d_in[8];
    const int*   wm       = (const int*)  d_in[9];
    const float* wwi      = (const float*)d_in[10];
    const float* sigma    = (const float*)d_in[11];
    const float* enc_w    = (const float*)d_in[12];
    const float* user_w   = (const float*)d_in[13];
    const float* wenc     = (const float*)d_in[14];
    const float* fcpt_w   = (const float*)d_in[15];
    const float* fcpt_b   = (const float*)d_in[16];
    const float* W_ih     = (const float*)d_in[17];
    const float* W_hh     = (const float*)d_in[18];
    const float* b_ih     = (const float*)d_in[19];
    const float* b_hh     = (const float*)d_in[20];
    const float* fc_w     = (const float*)d_in[21];
    const float* fc_b     = (const float*)d_in[22];
    float* out = (float*)d_out;

    void *pEnch, *pEncl, *pG1h, *pG1l, *pE2, *pTh, *pTl, *pG2h, *pG2l, *pT2;
    void *pUwh, *pUwl, *pP2, *pP3, *pCvec;
    void *pB1h, *pB1l, *pB2h, *pB2l, *pWihh, *pWihl, *pWhh16;
    void *pFcwA16, *pFcwBh, *pFcwBl, *pFcwCh, *pFcwCl;
    void *pOut16, *pHfin, *pW16, *pDen, *pOw16;
    cudaGetSymbolAddress(&pEnch, g_ench);  cudaGetSymbolAddress(&pEncl, g_encl);
    cudaGetSymbolAddress(&pG1h, g_G1h);    cudaGetSymbolAddress(&pG1l, g_G1l);
    cudaGetSymbolAddress(&pE2, g_E2);
    cudaGetSymbolAddress(&pTh, g_Th);      cudaGetSymbolAddress(&pTl, g_Tl);
    cudaGetSymbolAddress(&pG2h, g_G2h);    cudaGetSymbolAddress(&pG2l, g_G2l);
    cudaGetSymbolAddress(&pT2, g_T2);
    cudaGetSymbolAddress(&pUwh, g_uwh);    cudaGetSymbolAddress(&pUwl, g_uwl);
    cudaGetSymbolAddress(&pP2, g_P2);      cudaGetSymbolAddress(&pP3, g_P3);
    cudaGetSymbolAddress(&pCvec, g_cvec);
    cudaGetSymbolAddress(&pB1h, g_B1h);    cudaGetSymbolAddress(&pB1l, g_B1l);
    cudaGetSymbolAddress(&pB2h, g_B2h);    cudaGetSymbolAddress(&pB2l, g_B2l);
    cudaGetSymbolAddress(&pWihh, g_wihh);  cudaGetSymbolAddress(&pWihl, g_wihl);
    cudaGetSymbolAddress(&pWhh16, g_whh16);
    cudaGetSymbolAddress(&pFcwA16, g_fcwA16);
    cudaGetSymbolAddress(&pFcwBh, g_fcwBh); cudaGetSymbolAddress(&pFcwBl, g_fcwBl);
    cudaGetSymbolAddress(&pFcwCh, g_fcwCh); cudaGetSymbolAddress(&pFcwCl, g_fcwCl);
    cudaGetSymbolAddress(&pOut16, g_out16); cudaGetSymbolAddress(&pHfin, g_hfin);
    cudaGetSymbolAddress(&pW16, g_w16);    cudaGetSymbolAddress(&pDen, g_den);
    cudaGetSymbolAddress(&pOw16, g_ow16);

    cudaFuncSetAttribute(hmma_gemm_b, cudaFuncAttributeMaxDynamicSharedMemorySize, GEMM_SMEM);
    cudaFuncSetAttribute(hmma_gemm16, cudaFuncAttributeMaxDynamicSharedMemorySize, GEMM16_SMEM);
    cudaFuncSetAttribute(k_att_mma,   cudaFuncAttributeMaxDynamicSharedMemorySize, ATT_SMEM);
    cudaFuncSetAttribute(k_rnn3,      cudaFuncAttributeMaxDynamicSharedMemorySize, RNN3_SMEM);

    size_t yelems = (size_t)S_ * U_ * V_;
    float* hdst = ((size_t)out_size >= yelems + U_ * H_) ? (out + yelems)
                                                         : (float*)pHfin;

    /* fused prep: 3 launches */
    k_week<<<256, 256>>>(sigma, wwi, wm, wenc);
    k_prep1<<<450, 256>>>(user_w, act_user, fcpt_b, W_ih, b_ih, b_hh, W_hh, fcpt_w);
    k_prep2<<<512, 256>>>(enc_w, fc_w);

    /* batched small GEMMs: {G1, G2} */
    {
        GemmTask tg1 = { (const __nv_bfloat16*)pWihh, (const __nv_bfloat16*)pWihl,
                         (const __nv_bfloat16*)pB1h,  (const __nv_bfloat16*)pB1l,
                         nullptr, nullptr,
                         (__nv_bfloat16*)pG1h, (__nv_bfloat16*)pG1l, H_, 512, 2 };
        GemmTask tg2 = { (const __nv_bfloat16*)pWihh, (const __nv_bfloat16*)pWihl,
                         (const __nv_bfloat16*)pB2h,  (const __nv_bfloat16*)pB2l,
                         nullptr, nullptr,
                         (__nv_bfloat16*)pG2h, (__nv_bfloat16*)pG2l, H_, 256, 1 };
        hmma_gemm_b<<<12, 256, GEMM_SMEM>>>(tg1, tg2, tg1, tg1, 8, 4, 0, 0);
    }
    /* batched: {E2, T2, P2, P3} */
    {
        GemmTask te2 = { (const __nv_bfloat16*)pEnch, (const __nv_bfloat16*)pEncl,
                         (const __nv_bfloat16*)pG1h,  (const __nv_bfloat16*)pG1l,
                         nullptr, (float*)pE2, nullptr, nullptr, H_, 512, 2 };
        GemmTask tt2 = { (const __nv_bfloat16*)pTh,   (const __nv_bfloat16*)pTl,
                         (const __nv_bfloat16*)pG2h,  (const __nv_bfloat16*)pG2l,
                         (const float*)pCvec, (float*)pT2, nullptr, nullptr, H2_, 512, 2 };
        GemmTask tp2 = { (const __nv_bfloat16*)pUwh,  (const __nv_bfloat16*)pUwl,
                         (const __nv_bfloat16*)pFcwBh, (const __nv_bfloat16*)pFcwBl,
                         nullptr, (float*)pP2, nullptr, nullptr, H_, V_, 20 };
        GemmTask tp3 = { (const __nv_bfloat16*)pTh,   (const __nv_bfloat16*)pTl,
                         (const __nv_bfloat16*)pFcwCh, (const __nv_bfloat16*)pFcwCl,
                         nullptr, (float*)pP3, nullptr, nullptr, H2_, V_, 20 };
        hmma_gemm_b<<<144, 256, GEMM_SMEM>>>(te2, tt2, tp2, tp3, 80, 4, 20, 40);
    }

    /* RNN (clusters 0-7) + aux k_w / fcwA16 split (CTAs 32-131) */
    k_rnn3<<<132, 256, RNN3_SMEM>>>((const float*)pE2, (const float*)pT2,
                                    x, t_slot, (const __half*)pWhh16, h0,
                                    (__half*)pOut16, hdst,
                                    t, s, fc_w,
                                    (__half*)pW16, (float*)pDen,
                                    (__half*)pFcwA16, S_);

    /* attention */
    k_att_mma<<<dim3(2, 2, U_), 256, ATT_SMEM>>>(
        (const __half*)pW16, (const __half*)pOut16,
        (const float*)pDen, (__half*)pOw16);

    /* final projection */
    hmma_gemm16<<<dim3(VPAD / 256, MSU / 128), 256, GEMM16_SMEM>>>(
        (const __half*)pOw16, (const __half*)pFcwA16,
        fc_b, (const float*)pP2, (const float*)pP3, y_t_slot,
        out, H_, V_);
}